// round 1
// baseline (speedup 1.0000x reference)
#include <cuda_runtime.h>
#include <math.h>

#define EPSF 1e-8f
#define LAMF 1e-3f

// ---------------- static device scratch (no dynamic allocation) ----------------
__device__ float d_y[64 * 16 * 16 * 64];           // conv1+bn+relu, NHWC
__device__ float d_pose_prim[64 * 16 * 16 * 128];  // (b,h,w,8,16)
__device__ float d_a_prim[64 * 16 * 16 * 8];       // (b,h,w,8)
__device__ float d_pose1[64 * 7 * 7 * 16 * 16];    // (b,7,7,16,16)
__device__ float d_a1[64 * 7 * 7 * 16];
__device__ float d_pose2[64 * 5 * 5 * 16 * 16];
__device__ float d_a2[64 * 5 * 5 * 16];
// single reusable vote buffer (max: caps2 = 1600 * 144*16*16 = 58,982,400 floats)
__device__ float d_vbuf[58982400];

// ---------------- stage 1: conv 5x5 s2 p2 + BN + ReLU ----------------
__global__ void __launch_bounds__(256) conv1_bn_relu_kernel(
    const float* __restrict__ x, const float* __restrict__ w,
    const float* __restrict__ bconv, const float* __restrict__ g,
    const float* __restrict__ bb, const float* __restrict__ mean,
    const float* __restrict__ var)
{
    int idx = blockIdx.x * blockDim.x + threadIdx.x;  // (b, oh, ow, co)
    if (idx >= 64 * 16 * 16 * 64) return;
    int co = idx & 63;
    int ow = (idx >> 6) & 15;
    int oh = (idx >> 10) & 15;
    int b  = idx >> 14;
    float acc = bconv[co];
    const float* xp = x + b * 1024;
    const float* wp = w + co * 25;
#pragma unroll
    for (int kh = 0; kh < 5; kh++) {
        int ih = oh * 2 - 2 + kh;
        if (ih < 0 || ih >= 32) continue;
#pragma unroll
        for (int kw = 0; kw < 5; kw++) {
            int iw = ow * 2 - 2 + kw;
            if (iw < 0 || iw >= 32) continue;
            acc += xp[ih * 32 + iw] * wp[kh * 5 + kw];
        }
    }
    float inv_std = rsqrtf(var[co] + 1e-3f);
    float yv = (acc - mean[co]) * (g[co] * inv_std) + bb[co];
    d_y[idx] = fmaxf(yv, 0.0f);
}

// ---------------- stage 2: primary caps (two 1x1 convs) ----------------
__global__ void __launch_bounds__(160) prim_kernel(
    const float* __restrict__ pw, const float* __restrict__ pb,
    const float* __restrict__ aw, const float* __restrict__ ab)
{
    __shared__ float yv[64];
    int pos = blockIdx.x;  // 0..16383  (b,h,w)
    int tid = threadIdx.x;
    if (tid < 64) yv[tid] = d_y[pos * 64 + tid];
    __syncthreads();
    if (tid < 128) {
        float acc = pb[tid];
        const float* wr = pw + tid * 64;
#pragma unroll 8
        for (int c = 0; c < 64; c++) acc += yv[c] * wr[c];
        d_pose_prim[pos * 128 + tid] = acc;
    } else if (tid < 136) {
        int o = tid - 128;
        float acc = ab[o];
        const float* wr = aw + o * 64;
#pragma unroll 8
        for (int c = 0; c < 64; c++) acc += yv[c] * wr[c];
        d_a_prim[pos * 8 + o] = 1.0f / (1.0f + expf(-acc));
    }
}

// ---------------- fuzzy EM routing (MF=2, ITERS=2), block-cooperative ----------------
// v: [N*C*16] (global, per-block slice), a: smem [N]
template <int N, int C>
__device__ __forceinline__ void fuzzy_route(
    const float* __restrict__ v, const float* __restrict__ a,
    const float* __restrict__ beta_u, const float* __restrict__ beta_a,
    float* __restrict__ r, float* __restrict__ coeff,
    float* __restrict__ mu, float* __restrict__ sig,
    float* __restrict__ rowsum, float* __restrict__ colsum,
    float* __restrict__ aout)
{
    const int tid = threadIdx.x;
    const int T = 256;
    const float invC2 = 1.0f / ((float)C * (float)C);

    // ---- t = 0: rm = (1/C)^2 * a[i]
    for (int idx = tid; idx < N * C; idx += T) coeff[idx] = invC2 * a[idx / C];
    __syncthreads();
    for (int c = tid; c < C; c += T) {
        float s = 0.f;
        for (int i = 0; i < N; i++) s += coeff[i * C + c];
        colsum[c] = s;
    }
    __syncthreads();
    for (int idx = tid; idx < N * C; idx += T) coeff[idx] /= (colsum[idx % C] + EPSF);
    __syncthreads();
    // mu = sum_i coeff * v
    for (int idx = tid; idx < C * 16; idx += T) {
        int c = idx >> 4, pr = idx & 15;
        float s = 0.f;
        for (int i = 0; i < N; i++) s += coeff[i * C + c] * v[(i * C + c) * 16 + pr];
        mu[idx] = s;
    }
    __syncthreads();
    // dist -> inv -> r (fuzzy membership)
    for (int idx = tid; idx < N * C; idx += T) {
        int c = idx % C;
        const float* vp = v + idx * 16;
        const float* mp = mu + c * 16;
        float d = EPSF;
#pragma unroll
        for (int p = 0; p < 16; p++) { float t = vp[p] - mp[p]; d += t * t; }
        r[idx] = 1.0f / d;
    }
    __syncthreads();
    for (int i = tid; i < N; i += T) {
        float s = 0.f;
        for (int c = 0; c < C; c++) s += r[i * C + c];
        rowsum[i] = s;
    }
    __syncthreads();
    for (int idx = tid; idx < N * C; idx += T) r[idx] /= (rowsum[idx / C] + EPSF);
    __syncthreads();

    // ---- t = 1: rm = r^2 * a
    for (int idx = tid; idx < N * C; idx += T) {
        float rv = r[idx];
        coeff[idx] = rv * rv * a[idx / C];
    }
    __syncthreads();
    for (int c = tid; c < C; c += T) {  // colsum == r_sum (kept)
        float s = 0.f;
        for (int i = 0; i < N; i++) s += coeff[i * C + c];
        colsum[c] = s;
    }
    __syncthreads();
    for (int idx = tid; idx < N * C; idx += T) coeff[idx] /= (colsum[idx % C] + EPSF);
    __syncthreads();
    for (int idx = tid; idx < C * 16; idx += T) {
        int c = idx >> 4, pr = idx & 15;
        float s = 0.f;
        for (int i = 0; i < N; i++) s += coeff[i * C + c] * v[(i * C + c) * 16 + pr];
        mu[idx] = s;
    }
    __syncthreads();
    // sigma_sq
    for (int idx = tid; idx < C * 16; idx += T) {
        int c = idx >> 4, pr = idx & 15;
        float m = mu[idx];
        float s = 0.f;
        for (int i = 0; i < N; i++) {
            float t = v[(i * C + c) * 16 + pr] - m;
            s += coeff[i * C + c] * t * t;
        }
        sig[idx] = s + EPSF;
    }
    __syncthreads();
    // activation
    for (int c = tid; c < C; c += T) {
        float ls = 0.f;
#pragma unroll
        for (int p = 0; p < 16; p++) ls += logf(sig[c * 16 + p]);
        float cost = colsum[c] * (16.0f * beta_u[c] + 0.5f * ls);
        aout[c] = 1.0f / (1.0f + expf(-LAMF * (beta_a[c] - cost)));
    }
    __syncthreads();
}

// ---------------- conv caps layer (one block per output position) ----------------
// i = (kh*3 + kw)*Bi + bi ; v[i][c] = pp_i(4x4) @ W[i][c](4x4)
template <int N, int Bi, int C, int OHW, int IHW, int STRIDE>
__device__ __forceinline__ void conv_caps_impl(
    const float* __restrict__ pose_in, const float* __restrict__ a_in,
    const float* __restrict__ W, const float* __restrict__ bu,
    const float* __restrict__ ba, float* __restrict__ vglob,
    float* __restrict__ pose_out, float* __restrict__ a_out_g)
{
    __shared__ float pp[N * 16];
    __shared__ float a[N];
    __shared__ float r[N * C];
    __shared__ float coeff[N * C];
    __shared__ float mu[C * 16];
    __shared__ float sig[C * 16];
    __shared__ float rowsum[N];
    __shared__ float colsum[C];
    __shared__ float aout[C];

    const int n = blockIdx.x;
    const int b = n / (OHW * OHW);
    const int rem = n % (OHW * OHW);
    const int oh = rem / OHW, ow = rem % OHW;
    const int tid = threadIdx.x;
    const int T = 256;

    for (int idx = tid; idx < N * 16; idx += T) {
        int i = idx >> 4, pe = idx & 15;
        int kh = i / (3 * Bi), kw = (i / Bi) % 3, bi = i % Bi;
        int ih = oh * STRIDE + kh, iw = ow * STRIDE + kw;
        pp[idx] = pose_in[(((b * IHW + ih) * IHW + iw) * Bi + bi) * 16 + pe];
    }
    for (int i = tid; i < N; i += T) {
        int kh = i / (3 * Bi), kw = (i / Bi) % 3, bi = i % Bi;
        int ih = oh * STRIDE + kh, iw = ow * STRIDE + kw;
        a[i] = a_in[((b * IHW + ih) * IHW + iw) * Bi + bi];
    }
    __syncthreads();

    float* v = vglob + (size_t)n * (N * C * 16);
    for (int idx = tid; idx < N * C * 16; idx += T) {
        int i = idx / (C * 16);
        int c = (idx >> 4) % C;
        int pr = idx & 15;
        int p = pr >> 2, rr = pr & 3;
        const float* ppp = pp + i * 16 + p * 4;
        const float* wp = W + ((i * C + c) << 4) + rr;
        v[idx] = ppp[0] * wp[0] + ppp[1] * wp[4] + ppp[2] * wp[8] + ppp[3] * wp[12];
    }
    __syncthreads();

    fuzzy_route<N, C>(v, a, bu, ba, r, coeff, mu, sig, rowsum, colsum, aout);

    for (int idx = tid; idx < C * 16; idx += T)
        pose_out[(size_t)n * C * 16 + idx] = mu[idx];
    for (int c = tid; c < C; c += T) a_out_g[n * C + c] = aout[c];
}

__global__ void __launch_bounds__(256) caps1_kernel(
    const float* __restrict__ w1, const float* __restrict__ bu1, const float* __restrict__ ba1)
{
    conv_caps_impl<72, 8, 16, 7, 16, 2>(d_pose_prim, d_a_prim, w1, bu1, ba1,
                                        d_vbuf, d_pose1, d_a1);
}

__global__ void __launch_bounds__(256) caps2_kernel(
    const float* __restrict__ w2, const float* __restrict__ bu2, const float* __restrict__ ba2)
{
    conv_caps_impl<144, 16, 16, 5, 7, 1>(d_pose1, d_a1, w2, bu2, ba2,
                                         d_vbuf, d_pose2, d_a2);
}

// ---------------- class caps (one block per batch element) ----------------
__global__ void __launch_bounds__(256) class_kernel(
    const float* __restrict__ wc, const float* __restrict__ buc,
    const float* __restrict__ bac, float* __restrict__ out)
{
    __shared__ float a[400];
    __shared__ float r[400 * 10];
    __shared__ float coeff[400 * 10];
    __shared__ float mu[160];
    __shared__ float sig[160];
    __shared__ float rowsum[400];
    __shared__ float colsum[10];
    __shared__ float aout[10];

    const int b = blockIdx.x;
    const int tid = threadIdx.x;
    const int T = 256;
    float* v = d_vbuf + (size_t)b * 400 * 10 * 16;

    for (int i = tid; i < 400; i += T) a[i] = d_a2[b * 400 + i];

    for (int idx = tid; idx < 400 * 10 * 16; idx += T) {
        int nloc = idx / 160;
        int c = (idx >> 4) % 10;
        int pr = idx & 15;
        int p = pr >> 2, rr = pr & 3;
        int h = nloc / 80;
        int w_ = (nloc / 16) % 5;
        int i = nloc & 15;
        const float* pose = d_pose2 + ((size_t)(b * 400 + nloc)) * 16;
        const float* wp = wc + ((i * 10 + c) << 4) + rr;
        float s = pose[p * 4 + 0] * wp[0] + pose[p * 4 + 1] * wp[4] +
                  pose[p * 4 + 2] * wp[8] + pose[p * 4 + 3] * wp[12];
        if (pr == 0) s += (float)h * 0.2f;
        if (pr == 1) s += (float)w_ * 0.2f;
        v[idx] = s;
    }
    __syncthreads();

    fuzzy_route<400, 10>(v, a, buc, bac, r, coeff, mu, sig, rowsum, colsum, aout);

    for (int c = tid; c < 10; c += T) out[b * 10 + c] = aout[c];
}

// ---------------- launch ----------------
extern "C" void kernel_launch(void* const* d_in, const int* in_sizes, int n_in,
                              void* d_out, int out_size)
{
    const float* x        = (const float*)d_in[0];
    const float* conv1_w  = (const float*)d_in[1];
    const float* conv1_b  = (const float*)d_in[2];
    const float* bn_g     = (const float*)d_in[3];
    const float* bn_b     = (const float*)d_in[4];
    const float* bn_mean  = (const float*)d_in[5];
    const float* bn_var   = (const float*)d_in[6];
    const float* ppose_w  = (const float*)d_in[7];
    const float* ppose_b  = (const float*)d_in[8];
    const float* pa_w     = (const float*)d_in[9];
    const float* pa_b     = (const float*)d_in[10];
    const float* w1       = (const float*)d_in[11];
    const float* bu1      = (const float*)d_in[12];
    const float* ba1      = (const float*)d_in[13];
    const float* w2       = (const float*)d_in[14];
    const float* bu2      = (const float*)d_in[15];
    const float* ba2      = (const float*)d_in[16];
    const float* wc       = (const float*)d_in[17];
    const float* buc      = (const float*)d_in[18];
    const float* bac      = (const float*)d_in[19];
    float* out = (float*)d_out;

    conv1_bn_relu_kernel<<<4096, 256>>>(x, conv1_w, conv1_b, bn_g, bn_b, bn_mean, bn_var);
    prim_kernel<<<16384, 160>>>(ppose_w, ppose_b, pa_w, pa_b);
    caps1_kernel<<<3136, 256>>>(w1, bu1, ba1);
    caps2_kernel<<<1600, 256>>>(w2, bu2, ba2);
    class_kernel<<<64, 256>>>(wc, buc, bac, out);
}

// round 4
// speedup vs baseline: 1.5024x; 1.5024x over previous
#include <cuda_runtime.h>
#include <math.h>

#define EPSF 1e-8f
#define LAMF 1e-3f

// ---------------- static device scratch (no dynamic allocation) ----------------
__device__ float d_y[64 * 16 * 16 * 64];           // conv1+bn+relu, NHWC
__device__ float d_pose_prim[64 * 16 * 16 * 128];  // (b,h,w,8,16)
__device__ float d_a_prim[64 * 16 * 16 * 8];       // (b,h,w,8)
__device__ float d_pose1[64 * 7 * 7 * 16 * 16];    // (b,7,7,16,16)
__device__ float d_a1[64 * 7 * 7 * 16];
__device__ float d_pose2[64 * 5 * 5 * 16 * 16];
__device__ float d_a2[64 * 5 * 5 * 16];
// vote buffer (max: caps2 = 1600 * 144*16*16 = 58,982,400 floats)
__device__ float d_vbuf[58982400];

// ---------------- stage 1: conv 5x5 s2 p2 + BN + ReLU ----------------
__global__ void __launch_bounds__(256) conv1_bn_relu_kernel(
    const float* __restrict__ x, const float* __restrict__ w,
    const float* __restrict__ bconv, const float* __restrict__ g,
    const float* __restrict__ bb, const float* __restrict__ mean,
    const float* __restrict__ var)
{
    int idx = blockIdx.x * blockDim.x + threadIdx.x;  // (b, oh, ow, co)
    if (idx >= 64 * 16 * 16 * 64) return;
    int co = idx & 63;
    int ow = (idx >> 6) & 15;
    int oh = (idx >> 10) & 15;
    int b  = idx >> 14;
    float acc = bconv[co];
    const float* xp = x + b * 1024;
    const float* wp = w + co * 25;
#pragma unroll
    for (int kh = 0; kh < 5; kh++) {
        int ih = oh * 2 - 2 + kh;
        if (ih < 0 || ih >= 32) continue;
#pragma unroll
        for (int kw = 0; kw < 5; kw++) {
            int iw = ow * 2 - 2 + kw;
            if (iw < 0 || iw >= 32) continue;
            acc += xp[ih * 32 + iw] * wp[kh * 5 + kw];
        }
    }
    float inv_std = rsqrtf(var[co] + 1e-3f);
    float yv = (acc - mean[co]) * (g[co] * inv_std) + bb[co];
    d_y[idx] = fmaxf(yv, 0.0f);
}

// ---------------- stage 2: primary caps (two 1x1 convs) ----------------
__global__ void __launch_bounds__(160) prim_kernel(
    const float* __restrict__ pw, const float* __restrict__ pb,
    const float* __restrict__ aw, const float* __restrict__ ab)
{
    __shared__ float yv[64];
    int pos = blockIdx.x;  // 0..16383  (b,h,w)
    int tid = threadIdx.x;
    if (tid < 64) yv[tid] = d_y[pos * 64 + tid];
    __syncthreads();
    if (tid < 128) {
        float acc = pb[tid];
        const float* wr = pw + tid * 64;
#pragma unroll 8
        for (int c = 0; c < 64; c++) acc += yv[c] * wr[c];
        d_pose_prim[pos * 128 + tid] = acc;
    } else if (tid < 136) {
        int o = tid - 128;
        float acc = ab[o];
        const float* wr = aw + o * 64;
#pragma unroll 8
        for (int c = 0; c < 64; c++) acc += yv[c] * wr[c];
        d_a_prim[pos * 8 + o] = 1.0f / (1.0f + expf(-acc));
    }
}

// =====================================================================
// conv caps layer: one block per output position. v in GLOBAL (L2-hot),
// all v traffic float4, mu0 fused into vote build. Static smem only.
// =====================================================================
template <int N, int Bi, int C, int OHW, int IHW, int STRIDE, int THREADS>
__global__ void __launch_bounds__(THREADS) caps_kernel(
    const float* __restrict__ pose_in, const float* __restrict__ a_in,
    const float* __restrict__ W, const float* __restrict__ bu,
    const float* __restrict__ ba, float* __restrict__ vglob,
    float* __restrict__ pose_out, float* __restrict__ a_out_g)
{
    static_assert(C == 16, "caps path assumes C==16");
    constexpr int CP = 256;                 // C * 16
    constexpr int REPS4 = THREADS / 64;     // 4 (caps1) / 8 (caps2)

    __shared__ __align__(16) float pp[N * 16];
    __shared__ float a[N];
    __shared__ float wa[N];
    __shared__ float r[N * C];
    __shared__ __align__(16) float mu[CP];
    __shared__ float sig[CP];
    __shared__ __align__(16) float part[REPS4 * CP];   // >= 512 for colsum partials
    __shared__ float colsum[C];
    __shared__ float sA;

    const int tid = threadIdx.x;
    const int n = blockIdx.x;
    const int b = n / (OHW * OHW);
    const int rem = n % (OHW * OHW);
    const int oh = rem / OHW, ow = rem % OHW;

    // ---- gather pose patch (float4) + activations
    {
        float4* pp4 = (float4*)pp;
        for (int idx = tid; idx < N * 4; idx += THREADS) {
            int i = idx >> 2, q = idx & 3;
            int kh = i / (3 * Bi), kw = (i / Bi) % 3, bi = i % Bi;
            int ih = oh * STRIDE + kh, iw = ow * STRIDE + kw;
            pp4[idx] = ((const float4*)pose_in)[(((b * IHW + ih) * IHW + iw) * Bi + bi) * 4 + q];
        }
    }
    for (int i = tid; i < N; i += THREADS) {
        int kh = i / (3 * Bi), kw = (i / Bi) % 3, bi = i % Bi;
        int ih = oh * STRIDE + kh, iw = ow * STRIDE + kw;
        a[i] = a_in[((b * IHW + ih) * IHW + iw) * Bi + bi];
    }
    __syncthreads();

    // ---- asum -> t0 weights w_i = a_i / (asum + C^2*EPS)  (exact collapse of t=0 coeff)
    if (tid < 32) {
        float s = 0.f;
        for (int i = tid; i < N; i += 32) s += a[i];
#pragma unroll
        for (int o = 16; o; o >>= 1) s += __shfl_xor_sync(0xffffffffu, s, o);
        if (tid == 0) sA = s;
    }
    __syncthreads();
    {
        float denom = sA + EPSF * (float)(C * C);
        for (int i = tid; i < N; i += THREADS) wa[i] = a[i] / denom;
    }
    __syncthreads();

    float4* v4 = (float4*)(vglob + (size_t)n * (N * CP));
    const int g = tid & 63, rep = tid >> 6;
    const int gc = g >> 2, gp = g & 3;

    // ---- pass 1: votes (write v) fused with mu0 partial accumulation
    {
        const float4* pp4 = (const float4*)pp;
        float4 acc = make_float4(0.f, 0.f, 0.f, 0.f);
        for (int i = rep; i < N; i += REPS4) {
            float4 pv = pp4[i * 4 + gp];
            const float4* wp4 = (const float4*)(W + (i * C + gc) * 16);
            float4 w0 = wp4[0], w1 = wp4[1], w2 = wp4[2], w3 = wp4[3];
            float4 o;
            o.x = pv.x * w0.x + pv.y * w1.x + pv.z * w2.x + pv.w * w3.x;
            o.y = pv.x * w0.y + pv.y * w1.y + pv.z * w2.y + pv.w * w3.y;
            o.z = pv.x * w0.z + pv.y * w1.z + pv.z * w2.z + pv.w * w3.z;
            o.w = pv.x * w0.w + pv.y * w1.w + pv.z * w2.w + pv.w * w3.w;
            v4[(i * C + gc) * 4 + gp] = o;
            float wi = wa[i];
            acc.x += wi * o.x; acc.y += wi * o.y;
            acc.z += wi * o.z; acc.w += wi * o.w;
        }
        ((float4*)part)[rep * 64 + g] = acc;
    }
    __syncthreads();
    if (tid < CP) {
        float s = 0.f;
#pragma unroll
        for (int rr = 0; rr < REPS4; rr++) s += part[rr * CP + tid];
        mu[tid] = s;
    }
    __syncthreads();

    // ---- pass 2: dist -> inv  (float4 read of v, 4-lane shuffle reduce)
    for (int t = tid; t < N * C * 4; t += THREADS) {
        int pair = t >> 2, ch = t & 3;
        int c = pair & 15;
        float4 vv = v4[pair * 4 + ch];
        float4 mm = ((const float4*)mu)[c * 4 + ch];
        float dx = vv.x - mm.x, dy = vv.y - mm.y, dz = vv.z - mm.z, dw = vv.w - mm.w;
        float d = dx * dx + dy * dy + dz * dz + dw * dw;
        d += __shfl_xor_sync(0xffffffffu, d, 1);
        d += __shfl_xor_sync(0xffffffffu, d, 2);
        if (ch == 0) r[pair] = 1.0f / (d + EPSF);
    }
    __syncthreads();

    // ---- rowsum over C via 16-lane shuffle
    for (int t = tid; t < N * 16; t += THREADS) {
        int i = t >> 4, c = t & 15;
        float s = r[i * 16 + c];
        s += __shfl_xor_sync(0xffffffffu, s, 1);
        s += __shfl_xor_sync(0xffffffffu, s, 2);
        s += __shfl_xor_sync(0xffffffffu, s, 4);
        s += __shfl_xor_sync(0xffffffffu, s, 8);
        if (c == 0) wa[i] = 1.0f / (s + EPSF);
    }
    __syncthreads();

    // ---- coeff_unnorm = (r * rinv)^2 * a  (in place)
    for (int t = tid; t < N * C; t += THREADS) {
        int i = t >> 4;
        float val = r[t] * wa[i];
        r[t] = val * val * a[i];
    }
    __syncthreads();

    // ---- colsum (= r_sum): sub-strided partials (reuses part[0..512))
    for (int t = tid; t < 32 * C; t += THREADS) {
        int sub = t >> 4, c = t & 15;
        float s = 0.f;
        for (int i = sub; i < N; i += 32) s += r[i * C + c];
        part[t] = s;
    }
    __syncthreads();
    if (tid < C) {
        float s = 0.f;
#pragma unroll
        for (int sub = 0; sub < 32; sub++) s += part[sub * C + tid];
        colsum[tid] = s;
    }
    __syncthreads();

    // ---- normalize coeff
    for (int t = tid; t < N * C; t += THREADS) r[t] /= (colsum[t & 15] + EPSF);
    __syncthreads();

    // ---- pass 3: mu1 = sum_i coeff * v  (float4)
    {
        float4 acc = make_float4(0.f, 0.f, 0.f, 0.f);
        for (int i = rep; i < N; i += REPS4) {
            float cf = r[i * C + gc];
            float4 o = v4[(i * C + gc) * 4 + gp];
            acc.x += cf * o.x; acc.y += cf * o.y;
            acc.z += cf * o.z; acc.w += cf * o.w;
        }
        ((float4*)part)[rep * 64 + g] = acc;
    }
    __syncthreads();
    if (tid < CP) {
        float s = 0.f;
#pragma unroll
        for (int rr = 0; rr < REPS4; rr++) s += part[rr * CP + tid];
        mu[tid] = s;
    }
    __syncthreads();

    // ---- pass 4: sigma = sum_i coeff * (v - mu1)^2  (stable two-pass, float4)
    {
        float4 m = ((const float4*)mu)[g];
        float4 acc = make_float4(0.f, 0.f, 0.f, 0.f);
        for (int i = rep; i < N; i += REPS4) {
            float cf = r[i * C + gc];
            float4 o = v4[(i * C + gc) * 4 + gp];
            float dx = o.x - m.x, dy = o.y - m.y, dz = o.z - m.z, dw = o.w - m.w;
            acc.x += cf * dx * dx; acc.y += cf * dy * dy;
            acc.z += cf * dz * dz; acc.w += cf * dw * dw;
        }
        ((float4*)part)[rep * 64 + g] = acc;
    }
    __syncthreads();
    if (tid < CP) {
        float s = 0.f;
#pragma unroll
        for (int rr = 0; rr < REPS4; rr++) s += part[rr * CP + tid];
        sig[tid] = s + EPSF;
    }
    __syncthreads();

    // ---- activation + outputs
    if (tid < C) {
        float ls = 0.f;
#pragma unroll
        for (int p = 0; p < 16; p++) ls += logf(sig[tid * 16 + p]);
        float cost = colsum[tid] * (16.0f * bu[tid] + 0.5f * ls);
        a_out_g[n * C + tid] = 1.0f / (1.0f + expf(-LAMF * (ba[tid] - cost)));
    }
    {
        float4* po4 = (float4*)(pose_out + (size_t)n * CP);
        for (int t = tid; t < 64; t += THREADS) po4[t] = ((const float4*)mu)[t];
    }
}

// =====================================================================
// class caps: one block (1024 thr) per batch elem; v in global (L2),
// r/coeff in smem, replicated partial-sum reductions. Static smem only.
// =====================================================================
__global__ void __launch_bounds__(1024) class_kernel(
    const float* __restrict__ wc, const float* __restrict__ buc,
    const float* __restrict__ bac, float* __restrict__ out)
{
    constexpr int N = 400, C = 10, CP = 160, T = 1024, REPS = 6;
    __shared__ float a[N];
    __shared__ float wa[N];
    __shared__ float r[N * C];
    __shared__ __align__(16) float mu[CP];
    __shared__ float sig[CP];
    __shared__ float part[2 * REPS * CP];   // 1920 (>= 32*C)
    __shared__ float colsum[C];
    __shared__ float sA;

    const int b = blockIdx.x;
    const int tid = threadIdx.x;
    const float* pose = d_pose2 + (size_t)b * N * 16;
    float* v = d_vbuf + (size_t)b * N * C * 16;

    for (int i = tid; i < N; i += T) a[i] = d_a2[b * N + i];
    __syncthreads();

    if (tid < 32) {
        float s = 0.f;
        for (int i = tid; i < N; i += 32) s += a[i];
#pragma unroll
        for (int o = 16; o; o >>= 1) s += __shfl_xor_sync(0xffffffffu, s, o);
        if (tid == 0) sA = s;
    }

    // ---- votes (float4) with coord add
    for (int t = tid; t < N * C * 4; t += T) {
        int p = t & 3;
        int ic = t >> 2;              // nloc*10 + c
        int nloc = ic / 10, c = ic % 10;
        const float4 pv = *(const float4*)(pose + nloc * 16 + p * 4);
        const float* wp = wc + ((size_t)((nloc & 15) * 10 + c)) * 16;
        float4 w0 = *(const float4*)(wp);
        float4 w1 = *(const float4*)(wp + 4);
        float4 w2 = *(const float4*)(wp + 8);
        float4 w3 = *(const float4*)(wp + 12);
        float4 o;
        o.x = pv.x * w0.x + pv.y * w1.x + pv.z * w2.x + pv.w * w3.x;
        o.y = pv.x * w0.y + pv.y * w1.y + pv.z * w2.y + pv.w * w3.y;
        o.z = pv.x * w0.z + pv.y * w1.z + pv.z * w2.z + pv.w * w3.z;
        o.w = pv.x * w0.w + pv.y * w1.w + pv.z * w2.w + pv.w * w3.w;
        if (p == 0) {
            o.x += (float)(nloc / 80) * 0.2f;
            o.y += (float)((nloc / 16) % 5) * 0.2f;
        }
        *(float4*)(v + ic * 16 + p * 4) = o;
    }
    __syncthreads();

    {
        float denom = sA + EPSF * (float)(C * C);
        for (int i = tid; i < N; i += T) wa[i] = a[i] / denom;
    }
    __syncthreads();

    // ---- mu0
    {
        int rep = tid / CP, t2 = tid % CP;
        if (rep < REPS) {
            int c = t2 / 16, pr = t2 & 15;
            float s = 0.f;
            for (int i = rep; i < N; i += REPS) s += wa[i] * v[(i * C + c) * 16 + pr];
            part[rep * CP + t2] = s;
        }
    }
    __syncthreads();
    if (tid < CP) {
        float s = 0.f;
#pragma unroll
        for (int rr = 0; rr < REPS; rr++) s += part[rr * CP + tid];
        mu[tid] = s;
    }
    __syncthreads();

    // ---- dist -> inv
    for (int t = tid; t < N * C * 4; t += T) {
        int pair = t >> 2, ch = t & 3;
        int c = pair % C;
        float4 vv = *(const float4*)(v + pair * 16 + ch * 4);
        float4 mm = *(const float4*)(mu + c * 16 + ch * 4);
        float dx = vv.x - mm.x, dy = vv.y - mm.y, dz = vv.z - mm.z, dw = vv.w - mm.w;
        float d = dx * dx + dy * dy + dz * dz + dw * dw;
        d += __shfl_xor_sync(0xffffffffu, d, 1);
        d += __shfl_xor_sync(0xffffffffu, d, 2);
        if (ch == 0) r[pair] = 1.0f / (d + EPSF);
    }
    __syncthreads();

    // ---- rowsum over C=10
    for (int i = tid; i < N; i += T) {
        float s = 0.f;
#pragma unroll
        for (int c = 0; c < C; c++) s += r[i * C + c];
        wa[i] = 1.0f / (s + EPSF);
    }
    __syncthreads();

    for (int t = tid; t < N * C; t += T) {
        int i = t / C;
        float val = r[t] * wa[i];
        r[t] = val * val * a[i];
    }
    __syncthreads();

    // ---- colsum
    for (int t = tid; t < 32 * C; t += T) {
        int sub = t / C, c = t % C;
        float s = 0.f;
        for (int i = sub; i < N; i += 32) s += r[i * C + c];
        part[t] = s;
    }
    __syncthreads();
    if (tid < C) {
        float s = 0.f;
#pragma unroll
        for (int sub = 0; sub < 32; sub++) s += part[sub * C + tid];
        colsum[tid] = s;
    }
    __syncthreads();

    for (int t = tid; t < N * C; t += T) r[t] /= (colsum[t % C] + EPSF);
    __syncthreads();

    // ---- mu1
    {
        int rep = tid / CP, t2 = tid % CP;
        if (rep < REPS) {
            int c = t2 / 16, pr = t2 & 15;
            float s = 0.f;
            for (int i = rep; i < N; i += REPS)
                s += r[i * C + c] * v[(i * C + c) * 16 + pr];
            part[rep * CP + t2] = s;
        }
    }
    __syncthreads();
    if (tid < CP) {
        float s = 0.f;
#pragma unroll
        for (int rr = 0; rr < REPS; rr++) s += part[rr * CP + tid];
        mu[tid] = s;
    }
    __syncthreads();

    // ---- sigma (stable two-pass)
    {
        int rep = tid / CP, t2 = tid % CP;
        if (rep < REPS) {
            int c = t2 / 16, pr = t2 & 15;
            float m = mu[t2];
            float s = 0.f;
            for (int i = rep; i < N; i += REPS) {
                float d = v[(i * C + c) * 16 + pr] - m;
                s += r[i * C + c] * d * d;
            }
            part[rep * CP + t2] = s;
        }
    }
    __syncthreads();
    if (tid < CP) {
        float s = 0.f;
#pragma unroll
        for (int rr = 0; rr < REPS; rr++) s += part[rr * CP + tid];
        sig[tid] = s + EPSF;
    }
    __syncthreads();

    if (tid < C) {
        float ls = 0.f;
#pragma unroll
        for (int p = 0; p < 16; p++) ls += logf(sig[tid * 16 + p]);
        float cost = colsum[tid] * (16.0f * buc[tid] + 0.5f * ls);
        out[b * C + tid] = 1.0f / (1.0f + expf(-LAMF * (bac[tid] - cost)));
    }
}

// ---------------- launch (no attribute calls; all smem static <48KB) ----------------
extern "C" void kernel_launch(void* const* d_in, const int* in_sizes, int n_in,
                              void* d_out, int out_size)
{
    const float* x        = (const float*)d_in[0];
    const float* conv1_w  = (const float*)d_in[1];
    const float* conv1_b  = (const float*)d_in[2];
    const float* bn_g     = (const float*)d_in[3];
    const float* bn_b     = (const float*)d_in[4];
    const float* bn_mean  = (const float*)d_in[5];
    const float* bn_var   = (const float*)d_in[6];
    const float* ppose_w  = (const float*)d_in[7];
    const float* ppose_b  = (const float*)d_in[8];
    const float* pa_w     = (const float*)d_in[9];
    const float* pa_b     = (const float*)d_in[10];
    const float* w1       = (const float*)d_in[11];
    const float* bu1      = (const float*)d_in[12];
    const float* ba1      = (const float*)d_in[13];
    const float* w2       = (const float*)d_in[14];
    const float* bu2      = (const float*)d_in[15];
    const float* ba2      = (const float*)d_in[16];
    const float* wc       = (const float*)d_in[17];
    const float* buc      = (const float*)d_in[18];
    const float* bac      = (const float*)d_in[19];
    float* out = (float*)d_out;

    float* vbuf;
    cudaGetSymbolAddress((void**)&vbuf, d_vbuf);
    float* ppose;
    cudaGetSymbolAddress((void**)&ppose, d_pose_prim);
    float* aprim;
    cudaGetSymbolAddress((void**)&aprim, d_a_prim);
    float* pose1;
    cudaGetSymbolAddress((void**)&pose1, d_pose1);
    float* a1;
    cudaGetSymbolAddress((void**)&a1, d_a1);
    float* pose2;
    cudaGetSymbolAddress((void**)&pose2, d_pose2);
    float* a2;
    cudaGetSymbolAddress((void**)&a2, d_a2);

    conv1_bn_relu_kernel<<<4096, 256>>>(x, conv1_w, conv1_b, bn_g, bn_b, bn_mean, bn_var);
    prim_kernel<<<16384, 160>>>(ppose_w, ppose_b, pa_w, pa_b);
    caps_kernel<72, 8, 16, 7, 16, 2, 256><<<3136, 256>>>(
        ppose, aprim, w1, bu1, ba1, vbuf, pose1, a1);
    caps_kernel<144, 16, 16, 5, 7, 1, 512><<<1600, 512>>>(
        pose1, a1, w2, bu2, ba2, vbuf, pose2, a2);
    class_kernel<<<64, 1024>>>(wc, buc, bac, out);
}

// round 5
// speedup vs baseline: 4.0199x; 2.6757x over previous
#include <cuda_runtime.h>
#include <math.h>

#define EPSF 1e-8f
#define LAMF 1e-3f

// ---------------- static device scratch (no dynamic allocation) ----------------
__device__ float d_pose_prim[64 * 16 * 16 * 128];  // (b,h,w,8,16)
__device__ float d_a_prim[64 * 16 * 16 * 8];       // (b,h,w,8)
__device__ float d_pose1[64 * 7 * 7 * 16 * 16];    // (b,7,7,16,16)
__device__ float d_a1[64 * 7 * 7 * 16];
__device__ float d_pose2[64 * 5 * 5 * 16 * 16];
__device__ float d_a2[64 * 5 * 5 * 16];
// vote buffer (max: caps2 = 1600 * 144*16*16 = 58,982,400 floats)
__device__ float d_vbuf[58982400];

// =====================================================================
// fused conv5x5s2 + BN + ReLU + primary caps (two 1x1 convs)
// one block per (b, oh) row: 16 output positions
// =====================================================================
__global__ void __launch_bounds__(256) convprim_kernel(
    const float* __restrict__ x, const float* __restrict__ w,
    const float* __restrict__ bconv, const float* __restrict__ g,
    const float* __restrict__ bb, const float* __restrict__ mean,
    const float* __restrict__ var,
    const float* __restrict__ pw, const float* __restrict__ pb,
    const float* __restrict__ aw, const float* __restrict__ ab)
{
    __shared__ float xs[160];                     // 5 rows x 32 cols (zero-padded)
    __shared__ float wconv[1600];                 // 64 x 25
    __shared__ __align__(16) float yv[1024];      // 16 pos x 64 ch
    __shared__ __align__(16) float wp_s[128 * 68];// pose weights, padded rows
    __shared__ __align__(16) float wa_s[8 * 68];  // act weights, padded rows
    __shared__ float bnsc[64], bnbi[64];

    const int tid = threadIdx.x;
    const int blk = blockIdx.x;                   // b*16 + oh
    const int b = blk >> 4, oh = blk & 15;

    // ---- loads
    for (int t = tid; t < 160; t += 256) {
        int kh = t >> 5, iw = t & 31;
        int ih = oh * 2 - 2 + kh;
        xs[t] = (ih >= 0 && ih < 32) ? x[b * 1024 + ih * 32 + iw] : 0.0f;
    }
    for (int t = tid; t < 1600; t += 256) wconv[t] = w[t];
    for (int t = tid; t < 128 * 64; t += 256) {
        int o = t >> 6, c = t & 63;
        wp_s[o * 68 + c] = pw[t];
    }
    for (int t = tid; t < 8 * 64; t += 256) {
        int o = t >> 6, c = t & 63;
        wa_s[o * 68 + c] = aw[t];
    }
    if (tid < 64) {
        float sc = g[tid] * rsqrtf(var[tid] + 1e-3f);
        bnsc[tid] = sc;
        bnbi[tid] = bb[tid] - mean[tid] * sc;
    }
    __syncthreads();

    // ---- conv + BN + ReLU -> yv
    for (int t = tid; t < 1024; t += 256) {
        int co = t & 63, ow = t >> 6;
        float acc = bconv[co];
        const float* wr = wconv + co * 25;
#pragma unroll
        for (int kh = 0; kh < 5; kh++) {
#pragma unroll
            for (int kw = 0; kw < 5; kw++) {
                int iw = ow * 2 - 2 + kw;
                if (iw >= 0 && iw < 32)
                    acc += xs[kh * 32 + iw] * wr[kh * 5 + kw];
            }
        }
        yv[ow * 64 + co] = fmaxf(acc * bnsc[co] + bnbi[co], 0.0f);
    }
    __syncthreads();

    // ---- primary caps: 16 pos x (128 pose + 8 act)
    for (int t = tid; t < 16 * 136; t += 256) {
        int pos = t / 136, o = t % 136;
        const float4* y4 = (const float4*)(yv + pos * 64);
        int pg = (blk << 4) + pos;   // global position
        if (o < 128) {
            const float4* w4 = (const float4*)(wp_s + o * 68);
            float4 a4 = make_float4(0.f, 0.f, 0.f, 0.f);
#pragma unroll
            for (int j = 0; j < 16; j++) {
                float4 yy = y4[j], ww = w4[j];
                a4.x += yy.x * ww.x; a4.y += yy.y * ww.y;
                a4.z += yy.z * ww.z; a4.w += yy.w * ww.w;
            }
            d_pose_prim[pg * 128 + o] = pb[o] + a4.x + a4.y + a4.z + a4.w;
        } else {
            int o2 = o - 128;
            const float4* w4 = (const float4*)(wa_s + o2 * 68);
            float4 a4 = make_float4(0.f, 0.f, 0.f, 0.f);
#pragma unroll
            for (int j = 0; j < 16; j++) {
                float4 yy = y4[j], ww = w4[j];
                a4.x += yy.x * ww.x; a4.y += yy.y * ww.y;
                a4.z += yy.z * ww.z; a4.w += yy.w * ww.w;
            }
            float acc = ab[o2] + a4.x + a4.y + a4.z + a4.w;
            d_a_prim[pg * 8 + o2] = 1.0f / (1.0f + expf(-acc));
        }
    }
}

// =====================================================================
// conv caps layer: one block per output position. v in GLOBAL (L2-hot),
// 3 passes over v: (votes+mu0), dist, (mu1+sigma fused). Static smem.
// =====================================================================
template <int N, int Bi, int C, int OHW, int IHW, int STRIDE, int THREADS>
__global__ void __launch_bounds__(THREADS) caps_kernel(
    const float* __restrict__ pose_in, const float* __restrict__ a_in,
    const float* __restrict__ W, const float* __restrict__ bu,
    const float* __restrict__ ba, float* __restrict__ vglob,
    float* __restrict__ pose_out, float* __restrict__ a_out_g)
{
    static_assert(C == 16, "caps path assumes C==16");
    constexpr int CP = 256;                 // C * 16
    constexpr int REPS4 = THREADS / 64;     // 8

    __shared__ __align__(16) float pp[N * 16];
    __shared__ float a[N];
    __shared__ float wa[N];
    __shared__ float r[N * C];
    __shared__ __align__(16) float mu[CP];
    __shared__ float sig[CP];
    __shared__ __align__(16) float part[2 * REPS4 * CP];
    __shared__ float colsum[C];
    __shared__ float sA;

    const int tid = threadIdx.x;
    const int n = blockIdx.x;
    const int b = n / (OHW * OHW);
    const int rem = n % (OHW * OHW);
    const int oh = rem / OHW, ow = rem % OHW;

    // ---- gather pose patch (float4) + activations
    {
        float4* pp4 = (float4*)pp;
        for (int idx = tid; idx < N * 4; idx += THREADS) {
            int i = idx >> 2, q = idx & 3;
            int kh = i / (3 * Bi), kw = (i / Bi) % 3, bi = i % Bi;
            int ih = oh * STRIDE + kh, iw = ow * STRIDE + kw;
            pp4[idx] = ((const float4*)pose_in)[(((b * IHW + ih) * IHW + iw) * Bi + bi) * 4 + q];
        }
    }
    for (int i = tid; i < N; i += THREADS) {
        int kh = i / (3 * Bi), kw = (i / Bi) % 3, bi = i % Bi;
        int ih = oh * STRIDE + kh, iw = ow * STRIDE + kw;
        a[i] = a_in[((b * IHW + ih) * IHW + iw) * Bi + bi];
    }
    __syncthreads();

    // ---- asum -> t0 weights w_i = a_i / (asum + C^2*EPS)
    if (tid < 32) {
        float s = 0.f;
        for (int i = tid; i < N; i += 32) s += a[i];
#pragma unroll
        for (int o = 16; o; o >>= 1) s += __shfl_xor_sync(0xffffffffu, s, o);
        if (tid == 0) sA = s;
    }
    __syncthreads();
    {
        float denom = sA + EPSF * (float)(C * C);
        for (int i = tid; i < N; i += THREADS) wa[i] = a[i] / denom;
    }
    __syncthreads();

    float4* v4 = (float4*)(vglob + (size_t)n * (N * CP));
    const int g = tid & 63, rep = tid >> 6;
    const int gc = g >> 2, gp = g & 3;

    // ---- pass 1: votes (write v) fused with mu0 partials
    {
        const float4* pp4 = (const float4*)pp;
        float4 acc = make_float4(0.f, 0.f, 0.f, 0.f);
        for (int i = rep; i < N; i += REPS4) {
            float4 pv = pp4[i * 4 + gp];
            const float4* wp4 = (const float4*)(W + (i * C + gc) * 16);
            float4 w0 = wp4[0], w1 = wp4[1], w2 = wp4[2], w3 = wp4[3];
            float4 o;
            o.x = pv.x * w0.x + pv.y * w1.x + pv.z * w2.x + pv.w * w3.x;
            o.y = pv.x * w0.y + pv.y * w1.y + pv.z * w2.y + pv.w * w3.y;
            o.z = pv.x * w0.z + pv.y * w1.z + pv.z * w2.z + pv.w * w3.z;
            o.w = pv.x * w0.w + pv.y * w1.w + pv.z * w2.w + pv.w * w3.w;
            v4[(i * C + gc) * 4 + gp] = o;
            float wi = wa[i];
            acc.x += wi * o.x; acc.y += wi * o.y;
            acc.z += wi * o.z; acc.w += wi * o.w;
        }
        ((float4*)part)[rep * 64 + g] = acc;
    }
    __syncthreads();
    if (tid < CP) {
        float s = 0.f;
#pragma unroll
        for (int rr = 0; rr < REPS4; rr++) s += part[rr * CP + tid];
        mu[tid] = s;
    }
    __syncthreads();

    // ---- pass 2: dist -> inv (float4 + 4-lane shuffle reduce)
    for (int t = tid; t < N * C * 4; t += THREADS) {
        int pair = t >> 2, ch = t & 3;
        int c = pair & 15;
        float4 vv = v4[pair * 4 + ch];
        float4 mm = ((const float4*)mu)[c * 4 + ch];
        float dx = vv.x - mm.x, dy = vv.y - mm.y, dz = vv.z - mm.z, dw = vv.w - mm.w;
        float d = dx * dx + dy * dy + dz * dz + dw * dw;
        d += __shfl_xor_sync(0xffffffffu, d, 1);
        d += __shfl_xor_sync(0xffffffffu, d, 2);
        if (ch == 0) r[pair] = 1.0f / (d + EPSF);
    }
    __syncthreads();

    // ---- rowsum over C via 16-lane shuffle
    for (int t = tid; t < N * 16; t += THREADS) {
        int i = t >> 4, c = t & 15;
        float s = r[i * 16 + c];
        s += __shfl_xor_sync(0xffffffffu, s, 1);
        s += __shfl_xor_sync(0xffffffffu, s, 2);
        s += __shfl_xor_sync(0xffffffffu, s, 4);
        s += __shfl_xor_sync(0xffffffffu, s, 8);
        if (c == 0) wa[i] = 1.0f / (s + EPSF);
    }
    __syncthreads();

    // ---- coeff_unnorm = (r * rinv)^2 * a  (in place)
    for (int t = tid; t < N * C; t += THREADS) {
        int i = t >> 4;
        float val = r[t] * wa[i];
        r[t] = val * val * a[i];
    }
    __syncthreads();

    // ---- colsum (= r_sum): sub-strided partials
    for (int t = tid; t < 32 * C; t += THREADS) {
        int sub = t >> 4, c = t & 15;
        float s = 0.f;
        for (int i = sub; i < N; i += 32) s += r[i * C + c];
        part[t] = s;
    }
    __syncthreads();
    if (tid < C) {
        float s = 0.f;
#pragma unroll
        for (int sub = 0; sub < 32; sub++) s += part[sub * C + tid];
        colsum[tid] = s;
    }
    __syncthreads();

    // ---- normalize coeff
    for (int t = tid; t < N * C; t += THREADS) r[t] /= (colsum[t & 15] + EPSF);
    __syncthreads();

    // ---- pass 3 (fused): S1 = sum c*v, S2 = sum c*v^2
    {
        float4 a1 = make_float4(0.f, 0.f, 0.f, 0.f);
        float4 a2 = make_float4(0.f, 0.f, 0.f, 0.f);
        for (int i = rep; i < N; i += REPS4) {
            float cf = r[i * C + gc];
            float4 o = v4[(i * C + gc) * 4 + gp];
            a1.x += cf * o.x;       a1.y += cf * o.y;
            a1.z += cf * o.z;       a1.w += cf * o.w;
            a2.x += cf * o.x * o.x; a2.y += cf * o.y * o.y;
            a2.z += cf * o.z * o.z; a2.w += cf * o.w * o.w;
        }
        ((float4*)part)[rep * 64 + g] = a1;
        ((float4*)part)[(REPS4 + rep) * 64 + g] = a2;
    }
    __syncthreads();
    if (tid < CP) {
        float s1 = 0.f, s2 = 0.f;
#pragma unroll
        for (int rr = 0; rr < REPS4; rr++) {
            s1 += part[rr * CP + tid];
            s2 += part[(REPS4 + rr) * CP + tid];
        }
        mu[tid] = s1;
        float cs = colsum[tid >> 4];
        float rho = cs / (cs + EPSF);
        sig[tid] = fmaxf(s2 - s1 * s1 * (2.0f - rho), 0.0f) + EPSF;
    }
    __syncthreads();

    // ---- activation + outputs
    if (tid < C) {
        float ls = 0.f;
#pragma unroll
        for (int p = 0; p < 16; p++) ls += logf(sig[tid * 16 + p]);
        float cost = colsum[tid] * (16.0f * bu[tid] + 0.5f * ls);
        a_out_g[n * C + tid] = 1.0f / (1.0f + expf(-LAMF * (ba[tid] - cost)));
    }
    {
        float4* po4 = (float4*)(pose_out + (size_t)n * CP);
        for (int t = tid; t < 64; t += THREADS) po4[t] = ((const float4*)mu)[t];
    }
}

// =====================================================================
// class caps: one block (1024 thr) per batch elem; v in global (L2);
// mu1+sigma fused. Static smem only.
// =====================================================================
__global__ void __launch_bounds__(1024) class_kernel(
    const float* __restrict__ wc, const float* __restrict__ buc,
    const float* __restrict__ bac, float* __restrict__ out)
{
    constexpr int N = 400, C = 10, CP = 160, T = 1024, REPS = 6;
    __shared__ float a[N];
    __shared__ float wa[N];
    __shared__ float r[N * C];
    __shared__ __align__(16) float mu[CP];
    __shared__ float sig[CP];
    __shared__ float part[2 * REPS * CP];   // 1920 (>= 32*C)
    __shared__ float colsum[C];
    __shared__ float sA;

    const int b = blockIdx.x;
    const int tid = threadIdx.x;
    const float* pose = d_pose2 + (size_t)b * N * 16;
    float* v = d_vbuf + (size_t)b * N * C * 16;

    for (int i = tid; i < N; i += T) a[i] = d_a2[b * N + i];
    __syncthreads();

    if (tid < 32) {
        float s = 0.f;
        for (int i = tid; i < N; i += 32) s += a[i];
#pragma unroll
        for (int o = 16; o; o >>= 1) s += __shfl_xor_sync(0xffffffffu, s, o);
        if (tid == 0) sA = s;
    }

    // ---- votes (float4) with coord add
    for (int t = tid; t < N * C * 4; t += T) {
        int p = t & 3;
        int ic = t >> 2;              // nloc*10 + c
        int nloc = ic / 10, c = ic % 10;
        const float4 pv = *(const float4*)(pose + nloc * 16 + p * 4);
        const float* wp = wc + ((size_t)((nloc & 15) * 10 + c)) * 16;
        float4 w0 = *(const float4*)(wp);
        float4 w1 = *(const float4*)(wp + 4);
        float4 w2 = *(const float4*)(wp + 8);
        float4 w3 = *(const float4*)(wp + 12);
        float4 o;
        o.x = pv.x * w0.x + pv.y * w1.x + pv.z * w2.x + pv.w * w3.x;
        o.y = pv.x * w0.y + pv.y * w1.y + pv.z * w2.y + pv.w * w3.y;
        o.z = pv.x * w0.z + pv.y * w1.z + pv.z * w2.z + pv.w * w3.z;
        o.w = pv.x * w0.w + pv.y * w1.w + pv.z * w2.w + pv.w * w3.w;
        if (p == 0) {
            o.x += (float)(nloc / 80) * 0.2f;
            o.y += (float)((nloc / 16) % 5) * 0.2f;
        }
        *(float4*)(v + ic * 16 + p * 4) = o;
    }
    __syncthreads();

    {
        float denom = sA + EPSF * (float)(C * C);
        for (int i = tid; i < N; i += T) wa[i] = a[i] / denom;
    }
    __syncthreads();

    // ---- mu0
    {
        int rep = tid / CP, t2 = tid % CP;
        if (rep < REPS) {
            int c = t2 / 16, pr = t2 & 15;
            float s = 0.f;
            for (int i = rep; i < N; i += REPS) s += wa[i] * v[(i * C + c) * 16 + pr];
            part[rep * CP + t2] = s;
        }
    }
    __syncthreads();
    if (tid < CP) {
        float s = 0.f;
#pragma unroll
        for (int rr = 0; rr < REPS; rr++) s += part[rr * CP + tid];
        mu[tid] = s;
    }
    __syncthreads();

    // ---- dist -> inv
    for (int t = tid; t < N * C * 4; t += T) {
        int pair = t >> 2, ch = t & 3;
        int c = pair % C;
        float4 vv = *(const float4*)(v + pair * 16 + ch * 4);
        float4 mm = *(const float4*)(mu + c * 16 + ch * 4);
        float dx = vv.x - mm.x, dy = vv.y - mm.y, dz = vv.z - mm.z, dw = vv.w - mm.w;
        float d = dx * dx + dy * dy + dz * dz + dw * dw;
        d += __shfl_xor_sync(0xffffffffu, d, 1);
        d += __shfl_xor_sync(0xffffffffu, d, 2);
        if (ch == 0) r[pair] = 1.0f / (d + EPSF);
    }
    __syncthreads();

    // ---- rowsum over C=10
    for (int i = tid; i < N; i += T) {
        float s = 0.f;
#pragma unroll
        for (int c = 0; c < C; c++) s += r[i * C + c];
        wa[i] = 1.0f / (s + EPSF);
    }
    __syncthreads();

    for (int t = tid; t < N * C; t += T) {
        int i = t / C;
        float val = r[t] * wa[i];
        r[t] = val * val * a[i];
    }
    __syncthreads();

    // ---- colsum
    for (int t = tid; t < 32 * C; t += T) {
        int sub = t / C, c = t % C;
        float s = 0.f;
        for (int i = sub; i < N; i += 32) s += r[i * C + c];
        part[t] = s;
    }
    __syncthreads();
    if (tid < C) {
        float s = 0.f;
#pragma unroll
        for (int sub = 0; sub < 32; sub++) s += part[sub * C + tid];
        colsum[tid] = s;
    }
    __syncthreads();

    for (int t = tid; t < N * C; t += T) r[t] /= (colsum[t % C] + EPSF);
    __syncthreads();

    // ---- fused mu1 + sigma
    {
        int rep = tid / CP, t2 = tid % CP;
        if (rep < REPS) {
            int c = t2 / 16, pr = t2 & 15;
            float s1 = 0.f, s2 = 0.f;
            for (int i = rep; i < N; i += REPS) {
                float cf = r[i * C + c];
                float vv = v[(i * C + c) * 16 + pr];
                s1 += cf * vv;
                s2 += cf * vv * vv;
            }
            part[rep * CP + t2] = s1;
            part[(REPS + rep) * CP + t2] = s2;
        }
    }
    __syncthreads();
    if (tid < CP) {
        float s1 = 0.f, s2 = 0.f;
#pragma unroll
        for (int rr = 0; rr < REPS; rr++) {
            s1 += part[rr * CP + tid];
            s2 += part[(REPS + rr) * CP + tid];
        }
        int c = tid / 16;
        float cs = colsum[c];
        float rho = cs / (cs + EPSF);
        sig[tid] = fmaxf(s2 - s1 * s1 * (2.0f - rho), 0.0f) + EPSF;
    }
    __syncthreads();

    if (tid < C) {
        float ls = 0.f;
#pragma unroll
        for (int p = 0; p < 16; p++) ls += logf(sig[tid * 16 + p]);
        float cost = colsum[tid] * (16.0f * buc[tid] + 0.5f * ls);
        out[b * C + tid] = 1.0f / (1.0f + expf(-LAMF * (bac[tid] - cost)));
    }
}

// ---------------- launch (no attribute calls; all smem static <48KB) ----------------
extern "C" void kernel_launch(void* const* d_in, const int* in_sizes, int n_in,
                              void* d_out, int out_size)
{
    const float* x        = (const float*)d_in[0];
    const float* conv1_w  = (const float*)d_in[1];
    const float* conv1_b  = (const float*)d_in[2];
    const float* bn_g     = (const float*)d_in[3];
    const float* bn_b     = (const float*)d_in[4];
    const float* bn_mean  = (const float*)d_in[5];
    const float* bn_var   = (const float*)d_in[6];
    const float* ppose_w  = (const float*)d_in[7];
    const float* ppose_b  = (const float*)d_in[8];
    const float* pa_w     = (const float*)d_in[9];
    const float* pa_b     = (const float*)d_in[10];
    const float* w1       = (const float*)d_in[11];
    const float* bu1      = (const float*)d_in[12];
    const float* ba1      = (const float*)d_in[13];
    const float* w2       = (const float*)d_in[14];
    const float* bu2      = (const float*)d_in[15];
    const float* ba2      = (const float*)d_in[16];
    const float* wc       = (const float*)d_in[17];
    const float* buc      = (const float*)d_in[18];
    const float* bac      = (const float*)d_in[19];
    float* out = (float*)d_out;

    float *vbuf, *ppose, *aprim, *pose1, *a1, *pose2, *a2;
    cudaGetSymbolAddress((void**)&vbuf, d_vbuf);
    cudaGetSymbolAddress((void**)&ppose, d_pose_prim);
    cudaGetSymbolAddress((void**)&aprim, d_a_prim);
    cudaGetSymbolAddress((void**)&pose1, d_pose1);
    cudaGetSymbolAddress((void**)&a1, d_a1);
    cudaGetSymbolAddress((void**)&pose2, d_pose2);
    cudaGetSymbolAddress((void**)&a2, d_a2);

    convprim_kernel<<<1024, 256>>>(x, conv1_w, conv1_b, bn_g, bn_b, bn_mean, bn_var,
                                   ppose_w, ppose_b, pa_w, pa_b);
    caps_kernel<72, 8, 16, 7, 16, 2, 512><<<3136, 512>>>(
        ppose, aprim, w1, bu1, ba1, vbuf, pose1, a1);
    caps_kernel<144, 16, 16, 5, 7, 1, 512><<<1600, 512>>>(
        pose1, a1, w2, bu2, ba2, vbuf, pose2, a2);
    class_kernel<<<64, 1024>>>(wc, buc, bac, out);
}

// round 6
// speedup vs baseline: 4.4970x; 1.1187x over previous
#include <cuda_runtime.h>
#include <math.h>

#define EPSF 1e-8f
#define LAMF 1e-3f

// ---------------- static device scratch (no dynamic allocation) ----------------
__device__ float d_pose_prim[64 * 16 * 16 * 128];  // (b,h,w,8,16)
__device__ float d_a_prim[64 * 16 * 16 * 8];       // (b,h,w,8)
__device__ float d_pose1[64 * 7 * 7 * 16 * 16];    // (b,7,7,16,16)
__device__ float d_a1[64 * 7 * 7 * 16];
__device__ float d_pose2[64 * 5 * 5 * 16 * 16];
__device__ float d_a2[64 * 5 * 5 * 16];
// vote buffer: only class caps (64 * 400*10*16)
__device__ float d_vbuf[4096000];

// =====================================================================
// fused conv5x5s2 + BN + ReLU + primary caps (two 1x1 convs)
// one block per (b, oh) row: 16 output positions
// =====================================================================
__global__ void __launch_bounds__(256) convprim_kernel(
    const float* __restrict__ x, const float* __restrict__ w,
    const float* __restrict__ bconv, const float* __restrict__ g,
    const float* __restrict__ bb, const float* __restrict__ mean,
    const float* __restrict__ var,
    const float* __restrict__ pw, const float* __restrict__ pb,
    const float* __restrict__ aw, const float* __restrict__ ab)
{
    __shared__ float xs[160];                     // 5 rows x 32 cols (zero-padded)
    __shared__ float wconv[1600];                 // 64 x 25
    __shared__ __align__(16) float yv[1024];      // 16 pos x 64 ch
    __shared__ __align__(16) float wp_s[128 * 68];// pose weights, padded rows
    __shared__ __align__(16) float wa_s[8 * 68];  // act weights, padded rows
    __shared__ float bnsc[64], bnbi[64];

    const int tid = threadIdx.x;
    const int blk = blockIdx.x;                   // b*16 + oh
    const int b = blk >> 4, oh = blk & 15;

    for (int t = tid; t < 160; t += 256) {
        int kh = t >> 5, iw = t & 31;
        int ih = oh * 2 - 2 + kh;
        xs[t] = (ih >= 0 && ih < 32) ? x[b * 1024 + ih * 32 + iw] : 0.0f;
    }
    for (int t = tid; t < 1600; t += 256) wconv[t] = w[t];
    for (int t = tid; t < 128 * 64; t += 256) {
        int o = t >> 6, c = t & 63;
        wp_s[o * 68 + c] = pw[t];
    }
    for (int t = tid; t < 8 * 64; t += 256) {
        int o = t >> 6, c = t & 63;
        wa_s[o * 68 + c] = aw[t];
    }
    if (tid < 64) {
        float sc = g[tid] * rsqrtf(var[tid] + 1e-3f);
        bnsc[tid] = sc;
        bnbi[tid] = bb[tid] - mean[tid] * sc;
    }
    __syncthreads();

    for (int t = tid; t < 1024; t += 256) {
        int co = t & 63, ow = t >> 6;
        float acc = bconv[co];
        const float* wr = wconv + co * 25;
#pragma unroll
        for (int kh = 0; kh < 5; kh++) {
#pragma unroll
            for (int kw = 0; kw < 5; kw++) {
                int iw = ow * 2 - 2 + kw;
                if (iw >= 0 && iw < 32)
                    acc += xs[kh * 32 + iw] * wr[kh * 5 + kw];
            }
        }
        yv[ow * 64 + co] = fmaxf(acc * bnsc[co] + bnbi[co], 0.0f);
    }
    __syncthreads();

    for (int t = tid; t < 16 * 136; t += 256) {
        int pos = t / 136, o = t % 136;
        const float4* y4 = (const float4*)(yv + pos * 64);
        int pg = (blk << 4) + pos;
        if (o < 128) {
            const float4* w4 = (const float4*)(wp_s + o * 68);
            float4 a4 = make_float4(0.f, 0.f, 0.f, 0.f);
#pragma unroll
            for (int j = 0; j < 16; j++) {
                float4 yy = y4[j], ww = w4[j];
                a4.x += yy.x * ww.x; a4.y += yy.y * ww.y;
                a4.z += yy.z * ww.z; a4.w += yy.w * ww.w;
            }
            d_pose_prim[pg * 128 + o] = pb[o] + a4.x + a4.y + a4.z + a4.w;
        } else {
            int o2 = o - 128;
            const float4* w4 = (const float4*)(wa_s + o2 * 68);
            float4 a4 = make_float4(0.f, 0.f, 0.f, 0.f);
#pragma unroll
            for (int j = 0; j < 16; j++) {
                float4 yy = y4[j], ww = w4[j];
                a4.x += yy.x * ww.x; a4.y += yy.y * ww.y;
                a4.z += yy.z * ww.z; a4.w += yy.w * ww.w;
            }
            float acc = ab[o2] + a4.x + a4.y + a4.z + a4.w;
            d_a_prim[pg * 8 + o2] = 1.0f / (1.0f + expf(-acc));
        }
    }
}

// =====================================================================
// conv caps layer: one block per output position.
// Votes REGISTER-RESIDENT: each thread owns (c, pr-quarter) x strided i.
// No global vote buffer. Static smem only.
// =====================================================================
template <int N, int Bi, int C, int OHW, int IHW, int STRIDE>
__global__ void __launch_bounds__(512) caps_kernel(
    const float* __restrict__ pose_in, const float* __restrict__ a_in,
    const float* __restrict__ W, const float* __restrict__ bu,
    const float* __restrict__ ba,
    float* __restrict__ pose_out, float* __restrict__ a_out_g)
{
    static_assert(C == 16, "caps path assumes C==16");
    constexpr int THREADS = 512;
    constexpr int CP = 256;                 // C * 16
    constexpr int REPS4 = 8;                // THREADS / 64
    constexpr int ITER = N / REPS4;         // 9 (caps1) / 18 (caps2)
    static_assert(N % REPS4 == 0, "N divisible");

    __shared__ __align__(16) float pp[N * 16];
    __shared__ float a[N];
    __shared__ float wa[N];
    __shared__ float r[N * C];
    __shared__ __align__(16) float mu[CP];
    __shared__ float sig[CP];
    __shared__ __align__(16) float part[2 * REPS4 * CP];
    __shared__ float colsum[C];
    __shared__ float invcol[C];
    __shared__ float sA;

    const int tid = threadIdx.x;
    const int n = blockIdx.x;
    const int b = n / (OHW * OHW);
    const int rem = n % (OHW * OHW);
    const int oh = rem / OHW, ow = rem % OHW;

    // ---- gather pose patch (float4) + activations
    {
        float4* pp4s = (float4*)pp;
        for (int idx = tid; idx < N * 4; idx += THREADS) {
            int i = idx >> 2, q = idx & 3;
            int kh = i / (3 * Bi), kw = (i / Bi) % 3, bi = i % Bi;
            int ih = oh * STRIDE + kh, iw = ow * STRIDE + kw;
            pp4s[idx] = ((const float4*)pose_in)[(((b * IHW + ih) * IHW + iw) * Bi + bi) * 4 + q];
        }
    }
    for (int i = tid; i < N; i += THREADS) {
        int kh = i / (3 * Bi), kw = (i / Bi) % 3, bi = i % Bi;
        int ih = oh * STRIDE + kh, iw = ow * STRIDE + kw;
        a[i] = a_in[((b * IHW + ih) * IHW + iw) * Bi + bi];
    }
    __syncthreads();

    // ---- asum -> t0 weights w_i = a_i / (asum + C^2*EPS)
    if (tid < 32) {
        float s = 0.f;
        for (int i = tid; i < N; i += 32) s += a[i];
#pragma unroll
        for (int o = 16; o; o >>= 1) s += __shfl_xor_sync(0xffffffffu, s, o);
        if (tid == 0) sA = s;
    }
    __syncthreads();
    {
        float denom = sA + EPSF * (float)(C * C);
        for (int i = tid; i < N; i += THREADS) wa[i] = a[i] / denom;
    }
    __syncthreads();

    const int g = tid & 63, rep = tid >> 6;
    const int gc = g >> 2, gp = g & 3;

    float4 vreg[ITER];   // register-resident vote slice

    // ---- pass 1: build votes into registers + mu0 partials
    {
        const float4* pp4 = (const float4*)pp;
        const float4* W4 = (const float4*)W;
        float4 acc = make_float4(0.f, 0.f, 0.f, 0.f);
#pragma unroll
        for (int it = 0; it < ITER; it++) {
            int i = rep + it * REPS4;
            float4 pv = pp4[i * 4 + gp];
            const float4* wp4 = W4 + (i * C + gc) * 4;
            float4 w0 = wp4[0], w1 = wp4[1], w2 = wp4[2], w3 = wp4[3];
            float4 o;
            o.x = pv.x * w0.x + pv.y * w1.x + pv.z * w2.x + pv.w * w3.x;
            o.y = pv.x * w0.y + pv.y * w1.y + pv.z * w2.y + pv.w * w3.y;
            o.z = pv.x * w0.z + pv.y * w1.z + pv.z * w2.z + pv.w * w3.z;
            o.w = pv.x * w0.w + pv.y * w1.w + pv.z * w2.w + pv.w * w3.w;
            vreg[it] = o;
            float wi = wa[i];
            acc.x += wi * o.x; acc.y += wi * o.y;
            acc.z += wi * o.z; acc.w += wi * o.w;
        }
        ((float4*)part)[rep * 64 + g] = acc;
    }
    __syncthreads();
    if (tid < CP) {
        float s = 0.f;
#pragma unroll
        for (int rr = 0; rr < REPS4; rr++) s += part[rr * CP + tid];
        mu[tid] = s;
    }
    __syncthreads();

    // ---- pass 2: dist -> inv (registers + 4-lane shuffle reduce)
    {
        float4 mm = ((const float4*)mu)[gc * 4 + gp];
#pragma unroll
        for (int it = 0; it < ITER; it++) {
            int i = rep + it * REPS4;
            float4 vv = vreg[it];
            float dx = vv.x - mm.x, dy = vv.y - mm.y, dz = vv.z - mm.z, dw = vv.w - mm.w;
            float d = dx * dx + dy * dy + dz * dz + dw * dw;
            d += __shfl_xor_sync(0xffffffffu, d, 1);
            d += __shfl_xor_sync(0xffffffffu, d, 2);
            if (gp == 0) r[i * C + gc] = 1.0f / (d + EPSF);
        }
    }
    __syncthreads();

    // ---- rowsum over C via 16-lane shuffle -> wa = 1/rowsum
    for (int t = tid; t < N * 16; t += THREADS) {
        int i = t >> 4, c = t & 15;
        float s = r[i * 16 + c];
        s += __shfl_xor_sync(0xffffffffu, s, 1);
        s += __shfl_xor_sync(0xffffffffu, s, 2);
        s += __shfl_xor_sync(0xffffffffu, s, 4);
        s += __shfl_xor_sync(0xffffffffu, s, 8);
        if (c == 0) wa[i] = 1.0f / (s + EPSF);
    }
    __syncthreads();

    // ---- fused: coeff_unnorm = (r*rowinv)^2*a (written back) + colsum partials
    for (int t = tid; t < 32 * C; t += THREADS) {
        int sub = t >> 4, c = t & 15;
        float s = 0.f;
        for (int i = sub; i < N; i += 32) {
            float val = r[i * C + c] * wa[i];
            val = val * val * a[i];
            r[i * C + c] = val;
            s += val;
        }
        part[t] = s;
    }
    __syncthreads();
    if (tid < C) {
        float s = 0.f;
#pragma unroll
        for (int sub = 0; sub < 32; sub++) s += part[sub * C + tid];
        colsum[tid] = s;
        invcol[tid] = 1.0f / (s + EPSF);
    }
    __syncthreads();

    // ---- pass 3 (fused): S1 = sum c*v, S2 = sum c*v^2 (coeff normalized on the fly)
    {
        float ic = invcol[gc];
        float4 a1 = make_float4(0.f, 0.f, 0.f, 0.f);
        float4 a2 = make_float4(0.f, 0.f, 0.f, 0.f);
#pragma unroll
        for (int it = 0; it < ITER; it++) {
            int i = rep + it * REPS4;
            float cf = r[i * C + gc] * ic;
            float4 o = vreg[it];
            a1.x += cf * o.x;       a1.y += cf * o.y;
            a1.z += cf * o.z;       a1.w += cf * o.w;
            a2.x += cf * o.x * o.x; a2.y += cf * o.y * o.y;
            a2.z += cf * o.z * o.z; a2.w += cf * o.w * o.w;
        }
        ((float4*)part)[rep * 64 + g] = a1;
        ((float4*)part)[(REPS4 + rep) * 64 + g] = a2;
    }
    __syncthreads();
    if (tid < CP) {
        float s1 = 0.f, s2 = 0.f;
#pragma unroll
        for (int rr = 0; rr < REPS4; rr++) {
            s1 += part[rr * CP + tid];
            s2 += part[(REPS4 + rr) * CP + tid];
        }
        mu[tid] = s1;
        float cs = colsum[tid >> 4];
        float rho = cs / (cs + EPSF);
        sig[tid] = fmaxf(s2 - s1 * s1 * (2.0f - rho), 0.0f) + EPSF;
    }
    __syncthreads();

    // ---- activation + outputs
    if (tid < C) {
        float ls = 0.f;
#pragma unroll
        for (int p = 0; p < 16; p++) ls += logf(sig[tid * 16 + p]);
        float cost = colsum[tid] * (16.0f * bu[tid] + 0.5f * ls);
        a_out_g[n * C + tid] = 1.0f / (1.0f + expf(-LAMF * (ba[tid] - cost)));
    }
    {
        float4* po4 = (float4*)(pose_out + (size_t)n * CP);
        for (int t = tid; t < 64; t += THREADS) po4[t] = ((const float4*)mu)[t];
    }
}

// =====================================================================
// class caps: one block (1024 thr) per batch elem; v in global (L2);
// mu1+sigma fused. Static smem only.
// =====================================================================
__global__ void __launch_bounds__(1024) class_kernel(
    const float* __restrict__ wc, const float* __restrict__ buc,
    const float* __restrict__ bac, float* __restrict__ out)
{
    constexpr int N = 400, C = 10, CP = 160, T = 1024, REPS = 6;
    __shared__ float a[N];
    __shared__ float wa[N];
    __shared__ float r[N * C];
    __shared__ __align__(16) float mu[CP];
    __shared__ float sig[CP];
    __shared__ float part[2 * REPS * CP];
    __shared__ float colsum[C];
    __shared__ float sA;

    const int b = blockIdx.x;
    const int tid = threadIdx.x;
    const float* pose = d_pose2 + (size_t)b * N * 16;
    float* v = d_vbuf + (size_t)b * N * C * 16;

    for (int i = tid; i < N; i += T) a[i] = d_a2[b * N + i];
    __syncthreads();

    if (tid < 32) {
        float s = 0.f;
        for (int i = tid; i < N; i += 32) s += a[i];
#pragma unroll
        for (int o = 16; o; o >>= 1) s += __shfl_xor_sync(0xffffffffu, s, o);
        if (tid == 0) sA = s;
    }

    for (int t = tid; t < N * C * 4; t += T) {
        int p = t & 3;
        int ic = t >> 2;
        int nloc = ic / 10, c = ic % 10;
        const float4 pv = *(const float4*)(pose + nloc * 16 + p * 4);
        const float* wp = wc + ((size_t)((nloc & 15) * 10 + c)) * 16;
        float4 w0 = *(const float4*)(wp);
        float4 w1 = *(const float4*)(wp + 4);
        float4 w2 = *(const float4*)(wp + 8);
        float4 w3 = *(const float4*)(wp + 12);
        float4 o;
        o.x = pv.x * w0.x + pv.y * w1.x + pv.z * w2.x + pv.w * w3.x;
        o.y = pv.x * w0.y + pv.y * w1.y + pv.z * w2.y + pv.w * w3.y;
        o.z = pv.x * w0.z + pv.y * w1.z + pv.z * w2.z + pv.w * w3.z;
        o.w = pv.x * w0.w + pv.y * w1.w + pv.z * w2.w + pv.w * w3.w;
        if (p == 0) {
            o.x += (float)(nloc / 80) * 0.2f;
            o.y += (float)((nloc / 16) % 5) * 0.2f;
        }
        *(float4*)(v + ic * 16 + p * 4) = o;
    }
    __syncthreads();

    {
        float denom = sA + EPSF * (float)(C * C);
        for (int i = tid; i < N; i += T) wa[i] = a[i] / denom;
    }
    __syncthreads();

    {
        int rep = tid / CP, t2 = tid % CP;
        if (rep < REPS) {
            int c = t2 / 16, pr = t2 & 15;
            float s = 0.f;
            for (int i = rep; i < N; i += REPS) s += wa[i] * v[(i * C + c) * 16 + pr];
            part[rep * CP + t2] = s;
        }
    }
    __syncthreads();
    if (tid < CP) {
        float s = 0.f;
#pragma unroll
        for (int rr = 0; rr < REPS; rr++) s += part[rr * CP + tid];
        mu[tid] = s;
    }
    __syncthreads();

    for (int t = tid; t < N * C * 4; t += T) {
        int pair = t >> 2, ch = t & 3;
        int c = pair % C;
        float4 vv = *(const float4*)(v + pair * 16 + ch * 4);
        float4 mm = *(const float4*)(mu + c * 16 + ch * 4);
        float dx = vv.x - mm.x, dy = vv.y - mm.y, dz = vv.z - mm.z, dw = vv.w - mm.w;
        float d = dx * dx + dy * dy + dz * dz + dw * dw;
        d += __shfl_xor_sync(0xffffffffu, d, 1);
        d += __shfl_xor_sync(0xffffffffu, d, 2);
        if (ch == 0) r[pair] = 1.0f / (d + EPSF);
    }
    __syncthreads();

    for (int i = tid; i < N; i += T) {
        float s = 0.f;
#pragma unroll
        for (int c = 0; c < C; c++) s += r[i * C + c];
        wa[i] = 1.0f / (s + EPSF);
    }
    __syncthreads();

    for (int t = tid; t < N * C; t += T) {
        int i = t / C;
        float val = r[t] * wa[i];
        r[t] = val * val * a[i];
    }
    __syncthreads();

    for (int t = tid; t < 32 * C; t += T) {
        int sub = t / C, c = t % C;
        float s = 0.f;
        for (int i = sub; i < N; i += 32) s += r[i * C + c];
        part[t] = s;
    }
    __syncthreads();
    if (tid < C) {
        float s = 0.f;
#pragma unroll
        for (int sub = 0; sub < 32; sub++) s += part[sub * C + tid];
        colsum[tid] = s;
    }
    __syncthreads();

    for (int t = tid; t < N * C; t += T) r[t] /= (colsum[t % C] + EPSF);
    __syncthreads();

    {
        int rep = tid / CP, t2 = tid % CP;
        if (rep < REPS) {
            int c = t2 / 16, pr = t2 & 15;
            float s1 = 0.f, s2 = 0.f;
            for (int i = rep; i < N; i += REPS) {
                float cf = r[i * C + c];
                float vv = v[(i * C + c) * 16 + pr];
                s1 += cf * vv;
                s2 += cf * vv * vv;
            }
            part[rep * CP + t2] = s1;
            part[(REPS + rep) * CP + t2] = s2;
        }
    }
    __syncthreads();
    if (tid < CP) {
        float s1 = 0.f, s2 = 0.f;
#pragma unroll
        for (int rr = 0; rr < REPS; rr++) {
            s1 += part[rr * CP + tid];
            s2 += part[(REPS + rr) * CP + tid];
        }
        int c = tid / 16;
        float cs = colsum[c];
        float rho = cs / (cs + EPSF);
        sig[tid] = fmaxf(s2 - s1 * s1 * (2.0f - rho), 0.0f) + EPSF;
    }
    __syncthreads();

    if (tid < C) {
        float ls = 0.f;
#pragma unroll
        for (int p = 0; p < 16; p++) ls += logf(sig[tid * 16 + p]);
        float cost = colsum[tid] * (16.0f * buc[tid] + 0.5f * ls);
        out[b * C + tid] = 1.0f / (1.0f + expf(-LAMF * (bac[tid] - cost)));
    }
}

// ---------------- launch ----------------
extern "C" void kernel_launch(void* const* d_in, const int* in_sizes, int n_in,
                              void* d_out, int out_size)
{
    const float* x        = (const float*)d_in[0];
    const float* conv1_w  = (const float*)d_in[1];
    const float* conv1_b  = (const float*)d_in[2];
    const float* bn_g     = (const float*)d_in[3];
    const float* bn_b     = (const float*)d_in[4];
    const float* bn_mean  = (const float*)d_in[5];
    const float* bn_var   = (const float*)d_in[6];
    const float* ppose_w  = (const float*)d_in[7];
    const float* ppose_b  = (const float*)d_in[8];
    const float* pa_w     = (const float*)d_in[9];
    const float* pa_b     = (const float*)d_in[10];
    const float* w1       = (const float*)d_in[11];
    const float* bu1      = (const float*)d_in[12];
    const float* ba1      = (const float*)d_in[13];
    const float* w2       = (const float*)d_in[14];
    const float* bu2      = (const float*)d_in[15];
    const float* ba2      = (const float*)d_in[16];
    const float* wc       = (const float*)d_in[17];
    const float* buc      = (const float*)d_in[18];
    const float* bac      = (const float*)d_in[19];
    float* out = (float*)d_out;

    float *ppose, *aprim, *pose1, *a1, *pose2, *a2;
    cudaGetSymbolAddress((void**)&ppose, d_pose_prim);
    cudaGetSymbolAddress((void**)&aprim, d_a_prim);
    cudaGetSymbolAddress((void**)&pose1, d_pose1);
    cudaGetSymbolAddress((void**)&a1, d_a1);
    cudaGetSymbolAddress((void**)&pose2, d_pose2);
    cudaGetSymbolAddress((void**)&a2, d_a2);

    convprim_kernel<<<1024, 256>>>(x, conv1_w, conv1_b, bn_g, bn_b, bn_mean, bn_var,
                                   ppose_w, ppose_b, pa_w, pa_b);
    caps_kernel<72, 8, 16, 7, 16, 2><<<3136, 512>>>(
        ppose, aprim, w1, bu1, ba1, pose1, a1);
    caps_kernel<144, 16, 16, 5, 7, 1><<<1600, 512>>>(
        pose1, a1, w2, bu2, ba2, pose2, a2);
    class_kernel<<<64, 1024>>>(wc, buc, bac, out);
}

// round 8
// speedup vs baseline: 4.5442x; 1.0105x over previous
#include <cuda_runtime.h>
#include <math.h>

#define EPSF 1e-8f
#define LAMF 1e-3f

// ---------------- packed f32x2 helpers (Blackwell) ----------------
typedef unsigned long long u64t;
__device__ __forceinline__ u64t f2pack(float lo, float hi) {
    u64t r; asm("mov.b64 %0, {%1, %2};" : "=l"(r) : "f"(lo), "f"(hi)); return r;
}
__device__ __forceinline__ float2 f2unpack(u64t v) {
    float2 f; asm("mov.b64 {%0, %1}, %2;" : "=f"(f.x), "=f"(f.y) : "l"(v)); return f;
}
__device__ __forceinline__ u64t f2fma(u64t a, u64t b, u64t c) {
    u64t d; asm("fma.rn.f32x2 %0, %1, %2, %3;" : "=l"(d) : "l"(a), "l"(b), "l"(c)); return d;
}
__device__ __forceinline__ u64t f2mul(u64t a, u64t b) {
    u64t d; asm("mul.rn.f32x2 %0, %1, %2;" : "=l"(d) : "l"(a), "l"(b)); return d;
}
__device__ __forceinline__ u64t f2add(u64t a, u64t b) {
    u64t d; asm("add.rn.f32x2 %0, %1, %2;" : "=l"(d) : "l"(a), "l"(b)); return d;
}

// ---------------- static device scratch ----------------
__device__ float d_pose_prim[64 * 16 * 16 * 128];  // (b,h,w,8,16)
__device__ float d_a_prim[64 * 16 * 16 * 8];       // (b,h,w,8)
__device__ float d_pose1[64 * 7 * 7 * 16 * 16];
__device__ float d_a1[64 * 7 * 7 * 16];
__device__ float d_pose2[64 * 5 * 5 * 16 * 16];
__device__ float d_a2[64 * 5 * 5 * 16];
__device__ float d_vbuf[4096000];                  // class votes only

// =====================================================================
// fused conv5x5s2 + BN + ReLU + primary caps
// =====================================================================
__global__ void __launch_bounds__(256) convprim_kernel(
    const float* __restrict__ x, const float* __restrict__ w,
    const float* __restrict__ bconv, const float* __restrict__ g,
    const float* __restrict__ bb, const float* __restrict__ mean,
    const float* __restrict__ var,
    const float* __restrict__ pw, const float* __restrict__ pb,
    const float* __restrict__ aw, const float* __restrict__ ab)
{
    __shared__ float xs[160];
    __shared__ float wconv[1600];
    __shared__ __align__(16) float yv[1024];
    __shared__ __align__(16) float wp_s[128 * 68];
    __shared__ __align__(16) float wa_s[8 * 68];
    __shared__ float bnsc[64], bnbi[64];

    const int tid = threadIdx.x;
    const int blk = blockIdx.x;
    const int b = blk >> 4, oh = blk & 15;

    for (int t = tid; t < 160; t += 256) {
        int kh = t >> 5, iw = t & 31;
        int ih = oh * 2 - 2 + kh;
        xs[t] = (ih >= 0 && ih < 32) ? x[b * 1024 + ih * 32 + iw] : 0.0f;
    }
    for (int t = tid; t < 1600; t += 256) wconv[t] = w[t];
    for (int t = tid; t < 128 * 64; t += 256) {
        int o = t >> 6, c = t & 63;
        wp_s[o * 68 + c] = pw[t];
    }
    for (int t = tid; t < 8 * 64; t += 256) {
        int o = t >> 6, c = t & 63;
        wa_s[o * 68 + c] = aw[t];
    }
    if (tid < 64) {
        float sc = g[tid] * rsqrtf(var[tid] + 1e-3f);
        bnsc[tid] = sc;
        bnbi[tid] = bb[tid] - mean[tid] * sc;
    }
    __syncthreads();

    for (int t = tid; t < 1024; t += 256) {
        int co = t & 63, ow = t >> 6;
        float acc = bconv[co];
        const float* wr = wconv + co * 25;
#pragma unroll
        for (int kh = 0; kh < 5; kh++) {
#pragma unroll
            for (int kw = 0; kw < 5; kw++) {
                int iw = ow * 2 - 2 + kw;
                if (iw >= 0 && iw < 32)
                    acc += xs[kh * 32 + iw] * wr[kh * 5 + kw];
            }
        }
        yv[ow * 64 + co] = fmaxf(acc * bnsc[co] + bnbi[co], 0.0f);
    }
    __syncthreads();

    for (int t = tid; t < 16 * 136; t += 256) {
        int pos = t / 136, o = t % 136;
        const float4* y4 = (const float4*)(yv + pos * 64);
        int pg = (blk << 4) + pos;
        if (o < 128) {
            const float4* w4 = (const float4*)(wp_s + o * 68);
            float4 a4 = make_float4(0.f, 0.f, 0.f, 0.f);
#pragma unroll
            for (int j = 0; j < 16; j++) {
                float4 yy = y4[j], ww = w4[j];
                a4.x += yy.x * ww.x; a4.y += yy.y * ww.y;
                a4.z += yy.z * ww.z; a4.w += yy.w * ww.w;
            }
            d_pose_prim[pg * 128 + o] = pb[o] + a4.x + a4.y + a4.z + a4.w;
        } else {
            int o2 = o - 128;
            const float4* w4 = (const float4*)(wa_s + o2 * 68);
            float4 a4 = make_float4(0.f, 0.f, 0.f, 0.f);
#pragma unroll
            for (int j = 0; j < 16; j++) {
                float4 yy = y4[j], ww = w4[j];
                a4.x += yy.x * ww.x; a4.y += yy.y * ww.y;
                a4.z += yy.z * ww.z; a4.w += yy.w * ww.w;
            }
            float acc = ab[o2] + a4.x + a4.y + a4.z + a4.w;
            d_a_prim[pg * 8 + o2] = 1.0f / (1.0f + expf(-acc));
        }
    }
}

// =====================================================================
// conv caps layer: register-resident votes, packed f32x2 math
// =====================================================================
template <int N, int Bi, int C, int OHW, int IHW, int STRIDE>
__global__ void __launch_bounds__(512) caps_kernel(
    const float* __restrict__ pose_in, const float* __restrict__ a_in,
    const float* __restrict__ W, const float* __restrict__ bu,
    const float* __restrict__ ba,
    float* __restrict__ pose_out, float* __restrict__ a_out_g)
{
    static_assert(C == 16, "caps path assumes C==16");
    constexpr int THREADS = 512;
    constexpr int CP = 256;
    constexpr int REPS4 = 8;
    constexpr int ITER = N / REPS4;
    static_assert(N % REPS4 == 0, "N divisible");

    __shared__ __align__(16) float pp[N * 16];
    __shared__ float a[N];
    __shared__ float wa[N];
    __shared__ float r[N * C];
    __shared__ __align__(16) float mu[CP];
    __shared__ float sig[CP];
    __shared__ __align__(16) float part[2 * REPS4 * CP];
    __shared__ float colsum[C];
    __shared__ float invcol[C];
    __shared__ float sA;

    const int tid = threadIdx.x;
    const int n = blockIdx.x;
    const int b = n / (OHW * OHW);
    const int rem = n % (OHW * OHW);
    const int oh = rem / OHW, ow = rem % OHW;

    {
        float4* pp4s = (float4*)pp;
        for (int idx = tid; idx < N * 4; idx += THREADS) {
            int i = idx >> 2, q = idx & 3;
            int kh = i / (3 * Bi), kw = (i / Bi) % 3, bi = i % Bi;
            int ih = oh * STRIDE + kh, iw = ow * STRIDE + kw;
            pp4s[idx] = ((const float4*)pose_in)[(((b * IHW + ih) * IHW + iw) * Bi + bi) * 4 + q];
        }
    }
    for (int i = tid; i < N; i += THREADS) {
        int kh = i / (3 * Bi), kw = (i / Bi) % 3, bi = i % Bi;
        int ih = oh * STRIDE + kh, iw = ow * STRIDE + kw;
        a[i] = a_in[((b * IHW + ih) * IHW + iw) * Bi + bi];
    }
    __syncthreads();

    if (tid < 32) {
        float s = 0.f;
        for (int i = tid; i < N; i += 32) s += a[i];
#pragma unroll
        for (int o = 16; o; o >>= 1) s += __shfl_xor_sync(0xffffffffu, s, o);
        if (tid == 0) sA = s;
    }
    __syncthreads();
    {
        float denom = sA + EPSF * (float)(C * C);
        for (int i = tid; i < N; i += THREADS) wa[i] = a[i] / denom;
    }
    __syncthreads();

    const int g = tid & 63, rep = tid >> 6;
    const int gc = g >> 2, gp = g & 3;

    u64t vx[ITER], vz[ITER];   // packed votes: (x,y) and (z,w)

    // ---- pass 1: votes (packed) + mu0 partials
    {
        const float4* pp4 = (const float4*)pp;
        const ulonglong2* W2 = (const ulonglong2*)W;
        u64t accx = 0, accz = 0;
#pragma unroll
        for (int it = 0; it < ITER; it++) {
            int i = rep + it * REPS4;
            float4 pv = pp4[i * 4 + gp];
            u64t p0 = f2pack(pv.x, pv.x);
            u64t p1 = f2pack(pv.y, pv.y);
            u64t p2 = f2pack(pv.z, pv.z);
            u64t p3 = f2pack(pv.w, pv.w);
            const ulonglong2* wr = W2 + (size_t)(i * C + gc) * 4;
            ulonglong2 q0 = wr[0], q1 = wr[1], q2 = wr[2], q3 = wr[3];
            u64t oxy = f2mul(p0, q0.x);
            oxy = f2fma(p1, q1.x, oxy);
            oxy = f2fma(p2, q2.x, oxy);
            oxy = f2fma(p3, q3.x, oxy);
            u64t ozw = f2mul(p0, q0.y);
            ozw = f2fma(p1, q1.y, ozw);
            ozw = f2fma(p2, q2.y, ozw);
            ozw = f2fma(p3, q3.y, ozw);
            vx[it] = oxy; vz[it] = ozw;
            u64t wi2 = f2pack(wa[i], wa[i]);
            accx = f2fma(wi2, oxy, accx);
            accz = f2fma(wi2, ozw, accz);
        }
        ((ulonglong2*)part)[rep * 64 + g] = make_ulonglong2(accx, accz);
    }
    __syncthreads();
    if (tid < CP) {
        float s = 0.f;
#pragma unroll
        for (int rr = 0; rr < REPS4; rr++) s += part[rr * CP + tid];
        mu[tid] = s;
    }
    __syncthreads();

    // ---- pass 2: dist -> inv (packed)
    {
        float4 mm = ((const float4*)mu)[gc * 4 + gp];
        u64t nmx = f2pack(-mm.x, -mm.y);
        u64t nmz = f2pack(-mm.z, -mm.w);
#pragma unroll
        for (int it = 0; it < ITER; it++) {
            int i = rep + it * REPS4;
            u64t t1 = f2add(vx[it], nmx);
            u64t t2 = f2add(vz[it], nmz);
            u64t u = f2fma(t2, t2, f2mul(t1, t1));
            float2 uf = f2unpack(u);
            float d = uf.x + uf.y;
            d += __shfl_xor_sync(0xffffffffu, d, 1);
            d += __shfl_xor_sync(0xffffffffu, d, 2);
            if (gp == 0) r[i * C + gc] = 1.0f / (d + EPSF);
        }
    }
    __syncthreads();

    // ---- rowsum over C via 16-lane shuffle
    for (int t = tid; t < N * 16; t += THREADS) {
        int i = t >> 4, c = t & 15;
        float s = r[i * 16 + c];
        s += __shfl_xor_sync(0xffffffffu, s, 1);
        s += __shfl_xor_sync(0xffffffffu, s, 2);
        s += __shfl_xor_sync(0xffffffffu, s, 4);
        s += __shfl_xor_sync(0xffffffffu, s, 8);
        if (c == 0) wa[i] = 1.0f / (s + EPSF);
    }
    __syncthreads();

    // ---- fused coeff^2*a + colsum partials
    for (int t = tid; t < 32 * C; t += THREADS) {
        int sub = t >> 4, c = t & 15;
        float s = 0.f;
        for (int i = sub; i < N; i += 32) {
            float val = r[i * C + c] * wa[i];
            val = val * val * a[i];
            r[i * C + c] = val;
            s += val;
        }
        part[t] = s;
    }
    __syncthreads();
    if (tid < C) {
        float s = 0.f;
#pragma unroll
        for (int sub = 0; sub < 32; sub++) s += part[sub * C + tid];
        colsum[tid] = s;
        invcol[tid] = 1.0f / (s + EPSF);
    }
    __syncthreads();

    // ---- pass 3: fused S1/S2 (packed, normalize on the fly)
    {
        float icn = invcol[gc];
        u64t s1x = 0, s1z = 0, s2x = 0, s2z = 0;
#pragma unroll
        for (int it = 0; it < ITER; it++) {
            int i = rep + it * REPS4;
            float cf = r[i * C + gc] * icn;
            u64t cf2 = f2pack(cf, cf);
            s1x = f2fma(cf2, vx[it], s1x);
            s1z = f2fma(cf2, vz[it], s1z);
            s2x = f2fma(cf2, f2mul(vx[it], vx[it]), s2x);
            s2z = f2fma(cf2, f2mul(vz[it], vz[it]), s2z);
        }
        ((ulonglong2*)part)[rep * 64 + g] = make_ulonglong2(s1x, s1z);
        ((ulonglong2*)part)[(REPS4 + rep) * 64 + g] = make_ulonglong2(s2x, s2z);
    }
    __syncthreads();
    if (tid < CP) {
        float s1 = 0.f, s2 = 0.f;
#pragma unroll
        for (int rr = 0; rr < REPS4; rr++) {
            s1 += part[rr * CP + tid];
            s2 += part[(REPS4 + rr) * CP + tid];
        }
        mu[tid] = s1;
        float cs = colsum[tid >> 4];
        float rho = cs / (cs + EPSF);
        sig[tid] = fmaxf(s2 - s1 * s1 * (2.0f - rho), 0.0f) + EPSF;
    }
    __syncthreads();

    if (tid < C) {
        float ls = 0.f;
#pragma unroll
        for (int p = 0; p < 16; p++) ls += logf(sig[tid * 16 + p]);
        float cost = colsum[tid] * (16.0f * bu[tid] + 0.5f * ls);
        a_out_g[n * C + tid] = 1.0f / (1.0f + expf(-LAMF * (ba[tid] - cost)));
    }
    {
        float4* po4 = (float4*)(pose_out + (size_t)n * CP);
        for (int t = tid; t < 64; t += THREADS) po4[t] = ((const float4*)mu)[t];
    }
}

// =====================================================================
// class caps: votes+mu0 fused (fixed (c,p)-ownership), v in L2
// =====================================================================
__global__ void __launch_bounds__(1024) class_kernel(
    const float* __restrict__ wc, const float* __restrict__ buc,
    const float* __restrict__ bac, float* __restrict__ out)
{
    constexpr int N = 400, C = 10, CP = 160, T = 1024, REPS = 6;
    __shared__ float a[N];
    __shared__ float wa[N];
    __shared__ float r[N * C];
    __shared__ __align__(16) float mu[CP];
    __shared__ float sig[CP];
    __shared__ float part[2 * REPS * CP];
    __shared__ __align__(16) float partA[25 * CP];   // 16 KB
    __shared__ float colsum[C];
    __shared__ float sA;

    const int b = blockIdx.x;
    const int tid = threadIdx.x;
    const float* pose = d_pose2 + (size_t)b * N * 16;
    float* v = d_vbuf + (size_t)b * N * C * 16;

    for (int i = tid; i < N; i += T) a[i] = d_a2[b * N + i];
    __syncthreads();

    if (tid < 32) {
        float s = 0.f;
        for (int i = tid; i < N; i += 32) s += a[i];
#pragma unroll
        for (int o = 16; o; o >>= 1) s += __shfl_xor_sync(0xffffffffu, s, o);
        if (tid == 0) sA = s;
    }
    __syncthreads();
    {
        float denom = sA + EPSF * (float)(C * C);
        for (int i = tid; i < N; i += T) wa[i] = a[i] / denom;
    }
    __syncthreads();

    // ---- fused votes + mu0: thread owns fixed (c, p-quarter), strided i
    {
        const int g = tid % 40, rep = tid / 40;   // gc = g/4, gp = g%4
        if (rep < 25) {
            const int gc = g >> 2, gp = g & 3;
            float4 acc = make_float4(0.f, 0.f, 0.f, 0.f);
#pragma unroll
            for (int it = 0; it < 16; it++) {
                int i = rep + it * 25;
                float4 pv = ((const float4*)pose)[i * 4 + gp];
                const float4* wp4 = (const float4*)(wc + ((size_t)((i & 15) * 10 + gc)) * 16);
                float4 w0 = wp4[0], w1 = wp4[1], w2 = wp4[2], w3 = wp4[3];
                float4 o;
                o.x = pv.x * w0.x + pv.y * w1.x + pv.z * w2.x + pv.w * w3.x;
                o.y = pv.x * w0.y + pv.y * w1.y + pv.z * w2.y + pv.w * w3.y;
                o.z = pv.x * w0.z + pv.y * w1.z + pv.z * w2.z + pv.w * w3.z;
                o.w = pv.x * w0.w + pv.y * w1.w + pv.z * w2.w + pv.w * w3.w;
                if (gp == 0) {
                    o.x += (float)(i / 80) * 0.2f;
                    o.y += (float)((i / 16) % 5) * 0.2f;
                }
                *(float4*)(v + (i * C + gc) * 16 + gp * 4) = o;
                float wi = wa[i];
                acc.x += wi * o.x; acc.y += wi * o.y;
                acc.z += wi * o.z; acc.w += wi * o.w;
            }
            ((float4*)partA)[rep * 40 + g] = acc;
        }
    }
    __syncthreads();
    if (tid < CP) {
        float s = 0.f;
#pragma unroll
        for (int rr = 0; rr < 25; rr++) s += partA[rr * CP + tid];
        mu[tid] = s;
    }
    __syncthreads();

    // ---- dist -> inv
    for (int t = tid; t < N * C * 4; t += T) {
        int pair = t >> 2, ch = t & 3;
        int c = pair % C;
        float4 vv = *(const float4*)(v + pair * 16 + ch * 4);
        float4 mm = *(const float4*)(mu + c * 16 + ch * 4);
        float dx = vv.x - mm.x, dy = vv.y - mm.y, dz = vv.z - mm.z, dw = vv.w - mm.w;
        float d = dx * dx + dy * dy + dz * dz + dw * dw;
        d += __shfl_xor_sync(0xffffffffu, d, 1);
        d += __shfl_xor_sync(0xffffffffu, d, 2);
        if (ch == 0) r[pair] = 1.0f / (d + EPSF);
    }
    __syncthreads();

    // ---- rowsum over C=10
    for (int i = tid; i < N; i += T) {
        float s = 0.f;
#pragma unroll
        for (int c = 0; c < C; c++) s += r[i * C + c];
        wa[i] = 1.0f / (s + EPSF);
    }
    __syncthreads();

    for (int t = tid; t < N * C; t += T) {
        int i = t / C;
        float val = r[t] * wa[i];
        r[t] = val * val * a[i];
    }
    __syncthreads();

    for (int t = tid; t < 32 * C; t += T) {
        int sub = t / C, c = t % C;
        float s = 0.f;
        for (int i = sub; i < N; i += 32) s += r[i * C + c];
        part[t] = s;
    }
    __syncthreads();
    if (tid < C) {
        float s = 0.f;
#pragma unroll
        for (int sub = 0; sub < 32; sub++) s += part[sub * C + tid];
        colsum[tid] = s;
    }
    __syncthreads();

    for (int t = tid; t < N * C; t += T) r[t] /= (colsum[t % C] + EPSF);
    __syncthreads();

    // ---- fused mu1 + sigma
    {
        int rep = tid / CP, t2 = tid % CP;
        if (rep < REPS) {
            int c = t2 / 16, pr = t2 & 15;
            float s1 = 0.f, s2 = 0.f;
            for (int i = rep; i < N; i += REPS) {
                float cf = r[i * C + c];
                float vv = v[(i * C + c) * 16 + pr];
                s1 += cf * vv;
                s2 += cf * vv * vv;
            }
            part[rep * CP + t2] = s1;
            part[(REPS + rep) * CP + t2] = s2;
        }
    }
    __syncthreads();
    if (tid < CP) {
        float s1 = 0.f, s2 = 0.f;
#pragma unroll
        for (int rr = 0; rr < REPS; rr++) {
            s1 += part[rr * CP + tid];
            s2 += part[(REPS + rr) * CP + tid];
        }
        int c = tid / 16;
        float cs = colsum[c];
        float rho = cs / (cs + EPSF);
        sig[tid] = fmaxf(s2 - s1 * s1 * (2.0f - rho), 0.0f) + EPSF;
    }
    __syncthreads();

    if (tid < C) {
        float ls = 0.f;
#pragma unroll
        for (int p = 0; p < 16; p++) ls += logf(sig[tid * 16 + p]);
        float cost = colsum[tid] * (16.0f * buc[tid] + 0.5f * ls);
        out[b * C + tid] = 1.0f / (1.0f + expf(-LAMF * (bac[tid] - cost)));
    }
}

// ---------------- launch ----------------
extern "C" void kernel_launch(void* const* d_in, const int* in_sizes, int n_in,
                              void* d_out, int out_size)
{
    const float* x        = (const float*)d_in[0];
    const float* conv1_w  = (const float*)d_in[1];
    const float* conv1_b  = (const float*)d_in[2];
    const float* bn_g     = (const float*)d_in[3];
    const float* bn_b     = (const float*)d_in[4];
    const float* bn_mean  = (const float*)d_in[5];
    const float* bn_var   = (const float*)d_in[6];
    const float* ppose_w  = (const float*)d_in[7];
    const float* ppose_b  = (const float*)d_in[8];
    const float* pa_w     = (const float*)d_in[9];
    const float* pa_b     = (const float*)d_in[10];
    const float* w1       = (const float*)d_in[11];
    const float* bu1      = (const float*)d_in[12];
    const float* ba1      = (const float*)d_in[13];
    const float* w2       = (const float*)d_in[14];
    const float* bu2      = (const float*)d_in[15];
    const float* ba2      = (const float*)d_in[16];
    const float* wc       = (const float*)d_in[17];
    const float* buc      = (const float*)d_in[18];
    const float* bac      = (const float*)d_in[19];
    float* out = (float*)d_out;

    float *ppose, *aprim, *pose1, *a1, *pose2, *a2;
    cudaGetSymbolAddress((void**)&ppose, d_pose_prim);
    cudaGetSymbolAddress((void**)&aprim, d_a_prim);
    cudaGetSymbolAddress((void**)&pose1, d_pose1);
    cudaGetSymbolAddress((void**)&a1, d_a1);
    cudaGetSymbolAddress((void**)&pose2, d_pose2);
    cudaGetSymbolAddress((void**)&a2, d_a2);

    convprim_kernel<<<1024, 256>>>(x, conv1_w, conv1_b, bn_g, bn_b, bn_mean, bn_var,
                                   ppose_w, ppose_b, pa_w, pa_b);
    caps_kernel<72, 8, 16, 7, 16, 2><<<3136, 512>>>(
        ppose, aprim, w1, bu1, ba1, pose1, a1);
    caps_kernel<144, 16, 16, 5, 7, 1><<<1600, 512>>>(
        pose1, a1, w2, bu2, ba2, pose2, a2);
    class_kernel<<<64, 1024>>>(wc, buc, bac, out);
}